// round 6
// baseline (speedup 1.0000x reference)
#include <cuda_runtime.h>
#include <cuda_bf16.h>
#include <math.h>

// ---------------- device scratch (no allocations allowed) ----------------
__device__ __nv_bfloat16 g_Wb[32 * 64 * 64];  // [k][d][e] = bf16(Linv_k[d][e])
__device__ float g_t[32 * 64];                // t_k = Linv_k * centroid_k (fp32)
__device__ float g_nhc[32];                   // -0.5*(D*log2pi + logdet_k)
__device__ float g_part[4096];                // per-block partial sums

#define LOG2PI 1.8378770664093453f

// ---------------- prep: blocked-panel Cholesky + warp-parallel inverse -------
// grid = 32 (one block per component), block = 256 threads
__global__ void __launch_bounds__(256) prep_kernel(const float* __restrict__ cov,
                                                   const float* __restrict__ cen)
{
    __shared__ float A[64 * 65];    // cov -> L (lower); upper = symmetric junk
    __shared__ float Li[64 * 65];   // L^{-1}
    __shared__ float rd[64];        // 1 / L[m][m]
    __shared__ float dlog[64];

    const int k   = blockIdx.x;
    const int tid = threadIdx.x;
    const int l   = tid & 31;

    // load cov[k]
    for (int idx = tid; idx < 4096; idx += 256)
        A[(idx >> 6) * 65 + (idx & 63)] = cov[k * 4096 + idx];
    __syncthreads();

    // ---- blocked right-looking Cholesky: 8 panels of 8 columns ----
    #pragma unroll 1
    for (int p = 0; p < 8; ++p) {
        const int c0 = p * 8;

        // panel factorization: warp 0 only, fully register-resident
        if (tid < 32) {
            const int r0 = c0 + l;
            const int r1 = c0 + 32 + l;
            const bool act0 = (r0 < 64);
            const bool act1 = (r1 < 64);
            float a0[8], a1[8];
            #pragma unroll
            for (int m = 0; m < 8; ++m) {
                a0[m] = act0 ? A[r0 * 65 + c0 + m] : 0.f;
                a1[m] = act1 ? A[r1 * 65 + c0 + m] : 0.f;
            }
            #pragma unroll
            for (int jj = 0; jj < 8; ++jj) {
                // pivot diagonal (lane jj holds row c0+jj)
                const float d = __shfl_sync(0xffffffffu, a0[jj], jj);
                float rs = rsqrtf(d);
                rs = rs * (1.5f - 0.5f * d * rs * rs);   // Newton: fp32 accuracy
                // scale column jj (pivot lane gets sqrt(d))
                if (act0 && l >= jj) a0[jj] *= rs;
                if (act1)            a1[jj] *= rs;
                // multipliers L[c0+m][c0+jj] live in lane m's a0[jj]
                float lv[8];
                #pragma unroll
                for (int m = jj + 1; m < 8; ++m)
                    lv[m] = __shfl_sync(0xffffffffu, a0[jj], m);
                // rank-1 update restricted to panel columns
                #pragma unroll
                for (int m = jj + 1; m < 8; ++m) {
                    if (act0 && l > jj) a0[m] -= a0[jj] * lv[m];
                    if (act1)           a1[m] -= a1[jj] * lv[m];
                }
            }
            #pragma unroll
            for (int m = 0; m < 8; ++m) {
                if (act0) A[r0 * 65 + c0 + m] = a0[m];
                if (act1) A[r1 * 65 + c0 + m] = a1[m];
            }
        }
        __syncthreads();

        // trailing rank-8 update: rows/cols in [c0+8, 64), all 256 threads.
        // full square kept (upper = symmetric copies, preserves symmetry).
        const int R = 56 - c0;
        if (R > 0) {
            const int rr = tid >> 2;
            const int cq = tid & 3;
            if (rr < R) {
                const int r = c0 + 8 + rr;
                float pr[8];
                #pragma unroll
                for (int m = 0; m < 8; ++m) pr[m] = A[r * 65 + c0 + m];
                for (int cc = cq; cc < R; cc += 4) {
                    const int c = c0 + 8 + cc;
                    float s = A[r * 65 + c];
                    #pragma unroll
                    for (int m = 0; m < 8; ++m) s -= pr[m] * A[c * 65 + c0 + m];
                    A[r * 65 + c] = s;
                }
            }
        }
        __syncthreads();
    }

    if (tid < 64) {
        const float dii = A[tid * 65 + tid];
        dlog[tid] = 2.f * logf(dii);
        rd[tid]   = 1.0f / dii;
    }
    __syncthreads();
    if (tid == 0) {
        float ld = 0.f;
        #pragma unroll 4
        for (int m = 0; m < 64; ++m) ld += dlog[m];
        g_nhc[k] = -0.5f * (64.f * LOG2PI + ld);
    }

    // warp-parallel forward substitution: warp w solves columns w*8 .. w*8+7.
    // lane l owns rows l and l+32; 8 columns in flight per warp.
    {
        const int w = tid >> 5;
        const int r0 = l, r1 = l + 32;
        const int c0 = w * 8;
        float v0[8], v1[8];
        #pragma unroll
        for (int j = 0; j < 8; ++j) {
            v0[j] = (r0 == c0 + j) ? 1.f : 0.f;
            v1[j] = (r1 == c0 + j) ? 1.f : 0.f;
        }
        for (int m = 0; m < 64; ++m) {
            const float lr0 = (r0 > m) ? A[r0 * 65 + m] : 0.f;
            const float lr1 = (r1 > m) ? A[r1 * 65 + m] : 0.f;
            const float rdm = rd[m];
            const int   src = m & 31;
            const bool  lo  = (m < 32);
            #pragma unroll
            for (int j = 0; j < 8; ++j) {
                const float resid = lo ? v0[j] : v1[j];
                const float ym = __shfl_sync(0xffffffffu, resid, src) * rdm;
                v0[j] -= lr0 * ym;
                v1[j] -= lr1 * ym;
                if (l == src) Li[m * 65 + c0 + j] = ym;
            }
        }
    }
    __syncthreads();

    // t_k[i] = sum_e Li[i][e] * cen[k][e]  (fp32 exact shift)
    if (tid < 64) {
        float tv = 0.f;
        #pragma unroll 4
        for (int e = 0; e <= tid; ++e) tv += Li[tid * 65 + e] * cen[k * 64 + e];
        g_t[k * 64 + tid] = tv;
    }
    // bf16 W
    for (int idx = tid; idx < 4096; idx += 256) {
        const int d = idx >> 6, e = idx & 63;
        const float v = (e <= d) ? Li[d * 65 + e] : 0.f;
        g_Wb[k * 4096 + idx] = __float2bfloat16_rn(v);
    }
}

// ---------------- main: fused GEMM (bf16 HMMA) + square + weight ----------------
// grid = B/256, block = 256 threads (8 warps, each owns 32 batch rows)
#define SW 72   // bf16 smem row stride (144B): conflict-free fragment LDS

// dynamic smem layout (bytes)
#define OFF_XS   0                         // bf16 [256*SW]           36864
#define OFF_WS   36864                     // bf16 [2][64*SW]         18432
#define OFF_PS   55296                     // float [256*33]          33792
#define OFF_TS   89088                     // float [2][64]             512
#define OFF_NHC  89600                     // float [32]                128
#define OFF_LBL  89728                     // int   [256]              1024
#define OFF_RED  90752                     // float [256]              1024
#define SMEM_TOTAL 91776

__device__ __forceinline__ void cp_async16(void* dst, const void* src) {
    unsigned a = (unsigned)__cvta_generic_to_shared(dst);
    asm volatile("cp.async.ca.shared.global [%0], [%1], 16;\n" :: "r"(a), "l"(src));
}

__global__ void __launch_bounds__(256, 2) main_kernel(const float* __restrict__ emb,
                                                      const float* __restrict__ pi,
                                                      const int* __restrict__ labels)
{
    extern __shared__ char smem[];
    __nv_bfloat16* Xs  = (__nv_bfloat16*)(smem + OFF_XS);
    __nv_bfloat16* Ws  = (__nv_bfloat16*)(smem + OFF_WS);   // [buf][64*SW]
    float* Ps  = (float*)(smem + OFF_PS);
    float* ts  = (float*)(smem + OFF_TS);                    // [buf][64]
    float* nhc = (float*)(smem + OFF_NHC);
    int*   lbl = (int*)  (smem + OFF_LBL);
    float* red = (float*)(smem + OFF_RED);

    const int tid = threadIdx.x;
    const int b0  = blockIdx.x * 256;

    lbl[tid] = labels[b0 + tid];
    if (tid < 32) nhc[tid] = g_nhc[tid];
    __syncthreads();

    // gather embedding rows -> bf16 Xs
    {
        const int f4 = tid & 15, rg = tid >> 4;     // 16 float4/row, 16 rows/pass
        #pragma unroll
        for (int it = 0; it < 16; ++it) {
            const int row = rg + it * 16;
            const float4 v = *(const float4*)(emb + (size_t)lbl[row] * 64 + f4 * 4);
            __nv_bfloat162* p = (__nv_bfloat162*)&Xs[row * SW + f4 * 4];
            p[0] = __nv_bfloat162(__float2bfloat16_rn(v.x), __float2bfloat16_rn(v.y));
            p[1] = __nv_bfloat162(__float2bfloat16_rn(v.z), __float2bfloat16_rn(v.w));
        }
    }
    // gather pi rows
    {
        const int f4 = tid & 7, rg = tid >> 3;      // 8 float4/row, 32 rows/pass
        #pragma unroll
        for (int it = 0; it < 8; ++it) {
            const int row = rg + it * 32;
            const float4 v = *(const float4*)(pi + (size_t)lbl[row] * 32 + f4 * 4);
            Ps[row * 33 + f4 * 4 + 0] = v.x;
            Ps[row * 33 + f4 * 4 + 1] = v.y;
            Ps[row * 33 + f4 * 4 + 2] = v.z;
            Ps[row * 33 + f4 * 4 + 3] = v.w;
        }
    }

    const int w    = tid >> 5;        // warp 0..7 -> rows w*32 .. w*32+31
    const int lane = tid & 31;
    const int g    = lane >> 2;       // groupID 0..7
    const int t4   = lane & 3;
    const int rowA = w * 32 + g;      // fragment rows rowA(+8) and rowA+16(+24)

    // W / t prefetch (cp.async) into buffer b
    auto prefetch = [&](int k, int b) {
        const uint4* src = (const uint4*)(g_Wb + k * 4096);
        #pragma unroll
        for (int it = 0; it < 2; ++it) {
            const int idx = tid + it * 256;
            cp_async16(&Ws[b * 64 * SW + (idx >> 3) * SW + (idx & 7) * 8], &src[idx]);
        }
        if (tid < 16) cp_async16(&ts[b * 64 + tid * 4], &g_t[k * 64 + tid * 4]);
    };

    prefetch(0, 0);
    asm volatile("cp.async.commit_group;\n");

    float acc = 0.f;

    for (int k = 0; k < 32; ++k) {
        const int buf = k & 1;
        __syncthreads();                           // prior compute's reads done
        if (k + 1 < 32) prefetch(k + 1, buf ^ 1);
        asm volatile("cp.async.commit_group;\n");
        asm volatile("cp.async.wait_group 1;\n");  // buffer `buf` ready
        __syncthreads();

        const __nv_bfloat16* Wk = Ws + buf * 64 * SW;
        const float*        tsb = ts + buf * 64;

        // A fragments for both row-groups (reused across all j)
        unsigned aA[4][4], aB[4][4];
        #pragma unroll
        for (int es = 0; es < 4; ++es) {
            const int e0 = es * 16 + 2 * t4;
            aA[es][0] = *(const unsigned*)&Xs[(rowA)      * SW + e0];
            aA[es][1] = *(const unsigned*)&Xs[(rowA +  8) * SW + e0];
            aA[es][2] = *(const unsigned*)&Xs[(rowA)      * SW + e0 + 8];
            aA[es][3] = *(const unsigned*)&Xs[(rowA +  8) * SW + e0 + 8];
            aB[es][0] = *(const unsigned*)&Xs[(rowA + 16) * SW + e0];
            aB[es][1] = *(const unsigned*)&Xs[(rowA + 24) * SW + e0];
            aB[es][2] = *(const unsigned*)&Xs[(rowA + 16) * SW + e0 + 8];
            aB[es][3] = *(const unsigned*)&Xs[(rowA + 24) * SW + e0 + 8];
        }
        const float pA0 = Ps[(rowA)      * 33 + k];
        const float pA8 = Ps[(rowA +  8) * 33 + k];
        const float pB0 = Ps[(rowA + 16) * 33 + k];
        const float pB8 = Ps[(rowA + 24) * 33 + k];

        #pragma unroll
        for (int j = 0; j < 8; ++j) {              // n-tiles: d = j*8 .. j*8+7
            const float t0 = tsb[j * 8 + 2 * t4];
            const float t1 = tsb[j * 8 + 2 * t4 + 1];
            float cA0 = -t0, cA1 = -t1, cA2 = -t0, cA3 = -t1;
            float cB0 = -t0, cB1 = -t1, cB2 = -t0, cB3 = -t1;
            #pragma unroll
            for (int es = 0; es < 4; ++es) {
                const int e0 = es * 16 + 2 * t4;
                const unsigned b0 = *(const unsigned*)&Wk[(j * 8 + g) * SW + e0];
                const unsigned b1 = *(const unsigned*)&Wk[(j * 8 + g) * SW + e0 + 8];
                asm volatile(
                    "mma.sync.aligned.m16n8k16.row.col.f32.bf16.bf16.f32 "
                    "{%0,%1,%2,%3}, {%4,%5,%6,%7}, {%8,%9}, {%0,%1,%2,%3};\n"
                    : "+f"(cA0), "+f"(cA1), "+f"(cA2), "+f"(cA3)
                    : "r"(aA[es][0]), "r"(aA[es][1]), "r"(aA[es][2]), "r"(aA[es][3]),
                      "r"(b0), "r"(b1));
                asm volatile(
                    "mma.sync.aligned.m16n8k16.row.col.f32.bf16.bf16.f32 "
                    "{%0,%1,%2,%3}, {%4,%5,%6,%7}, {%8,%9}, {%0,%1,%2,%3};\n"
                    : "+f"(cB0), "+f"(cB1), "+f"(cB2), "+f"(cB3)
                    : "r"(aB[es][0]), "r"(aB[es][1]), "r"(aB[es][2]), "r"(aB[es][3]),
                      "r"(b0), "r"(b1));
            }
            acc = fmaf(pA0, fmaf(cA0, cA0, cA1 * cA1), acc);
            acc = fmaf(pA8, fmaf(cA2, cA2, cA3 * cA3), acc);
            acc = fmaf(pB0, fmaf(cB0, cB0, cB1 * cB1), acc);
            acc = fmaf(pB8, fmaf(cB2, cB2, cB3 * cB3), acc);
        }
    }
    acc *= -0.5f;

    // constant + logdet part: one thread per batch row
    {
        float c = 0.f;
        #pragma unroll
        for (int kk = 0; kk < 32; ++kk) c = fmaf(Ps[tid * 33 + kk], nhc[kk], c);
        acc += c;
    }

    // deterministic block reduction
    red[tid] = acc;
    __syncthreads();
    #pragma unroll
    for (int st = 128; st > 0; st >>= 1) {
        if (tid < st) red[tid] += red[tid + st];
        __syncthreads();
    }
    if (tid == 0) g_part[blockIdx.x] = red[0];
}

// ---------------- final reduce ----------------
__global__ void __launch_bounds__(1024) reduce_kernel(float* __restrict__ out, int nb)
{
    __shared__ float s[1024];
    const int t = threadIdx.x;
    float a = 0.f;
    for (int i = t; i < nb; i += 1024) a += g_part[i];
    s[t] = a;
    __syncthreads();
    #pragma unroll
    for (int st = 512; st > 0; st >>= 1) {
        if (t < st) s[t] += s[t + st];
        __syncthreads();
    }
    if (t == 0) out[0] = fabsf(s[0]);
}

// ---------------- launch ----------------
extern "C" void kernel_launch(void* const* d_in, const int* in_sizes, int n_in,
                              void* d_out, int out_size)
{
    const float* emb    = (const float*)d_in[0];   // (500000, 64)
    const float* cen    = (const float*)d_in[1];   // (32, 64)
    const float* cov    = (const float*)d_in[2];   // (32, 64, 64)
    const float* pi     = (const float*)d_in[3];   // (500000, 32)
    const int*   labels = (const int*)d_in[4];     // (B,)
    const int B  = in_sizes[4];
    const int nb = B / 256;

    static int configured = 0;
    if (!configured) {
        cudaFuncSetAttribute(main_kernel, cudaFuncAttributeMaxDynamicSharedMemorySize,
                             SMEM_TOTAL);
        configured = 1;
    }

    prep_kernel<<<32, 256>>>(cov, cen);
    main_kernel<<<nb, 256, SMEM_TOTAL>>>(emb, pi, labels);
    reduce_kernel<<<1, 1024>>>((float*)d_out, nb);
}

// round 7
// speedup vs baseline: 1.0593x; 1.0593x over previous
#include <cuda_runtime.h>
#include <cuda_bf16.h>
#include <math.h>

// ---------------- device scratch (no allocations allowed) ----------------
__device__ __nv_bfloat16 g_Wb[32 * 64 * 64];  // [k][d][e] = bf16(Linv_k[d][e])
__device__ float g_t[32 * 64];                // t_k = Linv_k * centroid_k (fp32)
__device__ float g_nhc[32];                   // -0.5*(D*log2pi + logdet_k)
__device__ float g_part[4096];                // per-block partial sums
__device__ int   g_ready;                     // # components prepped (reset at end)
__device__ int   g_done;                      // # blocks finished (reset at end)

#define LOG2PI 1.8378770664093453f

#define SW 72   // bf16 smem row stride (144B): conflict-free fragment LDS

// dynamic smem layout (bytes). Prep overlays [0, 33792) (inside Xs region,
// used strictly BEFORE the gather writes Xs).
#define OFF_XS   0                         // bf16 [256*SW]           36864
#define OFF_WS   36864                     // bf16 [2][64*SW]         18432
#define OFF_PS   55296                     // float [256*33]          33792
#define OFF_TS   89088                     // float [2][64]             512
#define OFF_NHC  89600                     // float [32]                128
#define OFF_LBL  89728                     // int   [256]              1024
#define OFF_RED  90752                     // float [256]              1024
#define OFF_FLG  91776                     // int   [1]                  16
#define SMEM_TOTAL 91808

__device__ __forceinline__ void cp_async16(void* dst, const void* src) {
    unsigned a = (unsigned)__cvta_generic_to_shared(dst);
    asm volatile("cp.async.ca.shared.global [%0], [%1], 16;\n" :: "r"(a), "l"(src));
}

// ---------------- prep (device fn): blocked Cholesky + warp-parallel inverse --
// Executes with the full 256-thread block; smem_raw = base of dynamic smem.
__device__ void do_prep(int k, const float* __restrict__ cov,
                        const float* __restrict__ cen, char* smem_raw, int tid)
{
    float* A    = (float*)smem_raw;          // 64*65 floats (stride 65)
    float* Li   = A  + 64 * 65;              // 64*65 floats
    float* rd   = Li + 64 * 65;              // 64
    float* dlog = rd + 64;                   // 64

    const int l = tid & 31;

    // load cov[k]
    for (int idx = tid; idx < 4096; idx += 256)
        A[(idx >> 6) * 65 + (idx & 63)] = cov[k * 4096 + idx];
    __syncthreads();

    // ---- blocked right-looking Cholesky: 8 panels of 8 columns ----
    #pragma unroll 1
    for (int p = 0; p < 8; ++p) {
        const int c0 = p * 8;

        // panel factorization: warp 0 only, register-resident
        if (tid < 32) {
            const int r0 = c0 + l;
            const int r1 = c0 + 32 + l;
            const bool act0 = (r0 < 64);
            const bool act1 = (r1 < 64);
            float a0[8], a1[8];
            #pragma unroll
            for (int m = 0; m < 8; ++m) {
                a0[m] = act0 ? A[r0 * 65 + c0 + m] : 0.f;
                a1[m] = act1 ? A[r1 * 65 + c0 + m] : 0.f;
            }
            #pragma unroll
            for (int jj = 0; jj < 8; ++jj) {
                const float d = __shfl_sync(0xffffffffu, a0[jj], jj);
                float rs = rsqrtf(d);
                rs = rs * (1.5f - 0.5f * d * rs * rs);   // Newton: fp32 accuracy
                if (act0 && l >= jj) a0[jj] *= rs;
                if (act1)            a1[jj] *= rs;
                float lv[8];
                #pragma unroll
                for (int m = jj + 1; m < 8; ++m)
                    lv[m] = __shfl_sync(0xffffffffu, a0[jj], m);
                #pragma unroll
                for (int m = jj + 1; m < 8; ++m) {
                    if (act0 && l > jj) a0[m] -= a0[jj] * lv[m];
                    if (act1)           a1[m] -= a1[jj] * lv[m];
                }
            }
            #pragma unroll
            for (int m = 0; m < 8; ++m) {
                if (act0) A[r0 * 65 + c0 + m] = a0[m];
                if (act1) A[r1 * 65 + c0 + m] = a1[m];
            }
        }
        __syncthreads();

        // trailing rank-8 update, LOWER TRIANGLE ONLY (c <= r); all 256 threads
        const int R = 56 - c0;
        if (R > 0) {
            const int rr = tid >> 2, cq = tid & 3;
            if (rr < R) {
                const int r = c0 + 8 + rr;
                float pr[8];
                #pragma unroll
                for (int m = 0; m < 8; ++m) pr[m] = A[r * 65 + c0 + m];
                for (int cc = cq; cc <= rr; cc += 4) {
                    const int c = c0 + 8 + cc;
                    float s = A[r * 65 + c];
                    #pragma unroll
                    for (int m = 0; m < 8; ++m) s -= pr[m] * A[c * 65 + c0 + m];
                    A[r * 65 + c] = s;
                }
            }
        }
        __syncthreads();
    }

    if (tid < 64) {
        const float dii = A[tid * 65 + tid];
        dlog[tid] = 2.f * logf(dii);
        rd[tid]   = 1.0f / dii;
    }
    __syncthreads();
    if (tid == 0) {
        float ld = 0.f;
        #pragma unroll 4
        for (int m = 0; m < 64; ++m) ld += dlog[m];
        g_nhc[k] = -0.5f * (64.f * LOG2PI + ld);
    }

    // warp-parallel forward substitution: warp w solves columns w*8 .. w*8+7
    {
        const int w = tid >> 5;
        const int r0 = l, r1 = l + 32;
        const int c0 = w * 8;
        float v0[8], v1[8];
        #pragma unroll
        for (int j = 0; j < 8; ++j) {
            v0[j] = (r0 == c0 + j) ? 1.f : 0.f;
            v1[j] = (r1 == c0 + j) ? 1.f : 0.f;
        }
        for (int m = 0; m < 64; ++m) {
            const float lr0 = (r0 > m) ? A[r0 * 65 + m] : 0.f;
            const float lr1 = (r1 > m) ? A[r1 * 65 + m] : 0.f;
            const float rdm = rd[m];
            const int   src = m & 31;
            const bool  lo  = (m < 32);
            #pragma unroll
            for (int j = 0; j < 8; ++j) {
                const float resid = lo ? v0[j] : v1[j];
                const float ym = __shfl_sync(0xffffffffu, resid, src) * rdm;
                v0[j] -= lr0 * ym;
                v1[j] -= lr1 * ym;
                if (l == src) Li[m * 65 + c0 + j] = ym;
            }
        }
    }
    __syncthreads();

    // t_k[i] = sum_e Li[i][e] * cen[k][e]  (fp32 exact shift)
    if (tid < 64) {
        float tv = 0.f;
        #pragma unroll 4
        for (int e = 0; e <= tid; ++e) tv += Li[tid * 65 + e] * cen[k * 64 + e];
        g_t[k * 64 + tid] = tv;
    }
    // bf16 W
    for (int idx = tid; idx < 4096; idx += 256) {
        const int d = idx >> 6, e = idx & 63;
        const float v = (e <= d) ? Li[d * 65 + e] : 0.f;
        g_Wb[k * 4096 + idx] = __float2bfloat16_rn(v);
    }
    __syncthreads();   // A/Li free for reuse (next component or gather)
}

// ---------------- single fused kernel ----------------------------------------
// grid = B/256, block = 256 threads (8 warps, each owns 32 batch rows)
__global__ void __launch_bounds__(256, 2) fused_kernel(const float* __restrict__ emb,
                                                       const float* __restrict__ cen,
                                                       const float* __restrict__ cov,
                                                       const float* __restrict__ pi,
                                                       const int* __restrict__ labels,
                                                       float* __restrict__ out)
{
    extern __shared__ char smem[];
    __nv_bfloat16* Xs  = (__nv_bfloat16*)(smem + OFF_XS);
    __nv_bfloat16* Ws  = (__nv_bfloat16*)(smem + OFF_WS);   // [buf][64*SW]
    float* Ps  = (float*)(smem + OFF_PS);
    float* ts  = (float*)(smem + OFF_TS);                    // [buf][64]
    float* nhc = (float*)(smem + OFF_NHC);
    int*   lbl = (int*)  (smem + OFF_LBL);
    float* red = (float*)(smem + OFF_RED);
    int*   flg = (int*)  (smem + OFF_FLG);

    const int tid = threadIdx.x;
    const int nb  = gridDim.x;
    const int b0  = blockIdx.x * 256;

    lbl[tid] = labels[b0 + tid];   // high smem region: safe alongside prep

    // ---- phase 0: blocks < 32 prep one component each (overlaps others' gather)
    if (blockIdx.x < 32) {
        for (int kk = blockIdx.x; kk < 32; kk += nb) {   // nb>=32 normally: one iter
            do_prep(kk, cov, cen, smem, tid);
            if (tid == 0) {
                __threadfence();
                atomicAdd(&g_ready, 1);
            }
            __syncthreads();
        }
    }
    __syncthreads();

    // ---- phase 1: gather embedding rows -> bf16 Xs (independent of prep)
    {
        const int f4 = tid & 15, rg = tid >> 4;
        #pragma unroll
        for (int it = 0; it < 16; ++it) {
            const int row = rg + it * 16;
            const float4 v = *(const float4*)(emb + (size_t)lbl[row] * 64 + f4 * 4);
            __nv_bfloat162* p = (__nv_bfloat162*)&Xs[row * SW + f4 * 4];
            p[0] = __nv_bfloat162(__float2bfloat16_rn(v.x), __float2bfloat16_rn(v.y));
            p[1] = __nv_bfloat162(__float2bfloat16_rn(v.z), __float2bfloat16_rn(v.w));
        }
    }
    {
        const int f4 = tid & 7, rg = tid >> 3;
        #pragma unroll
        for (int it = 0; it < 8; ++it) {
            const int row = rg + it * 32;
            const float4 v = *(const float4*)(pi + (size_t)lbl[row] * 32 + f4 * 4);
            Ps[row * 33 + f4 * 4 + 0] = v.x;
            Ps[row * 33 + f4 * 4 + 1] = v.y;
            Ps[row * 33 + f4 * 4 + 2] = v.z;
            Ps[row * 33 + f4 * 4 + 3] = v.w;
        }
    }

    // ---- phase 2: wait for all 32 components
    if (tid == 0) {
        while (atomicAdd(&g_ready, 0) < 32) { __nanosleep(100); }
    }
    __syncthreads();
    __threadfence();                 // acquire: order g_Wb/g_t/g_nhc reads
    if (tid < 32) nhc[tid] = g_nhc[tid];

    // ---- phase 3: fused GEMM (bf16 HMMA) + square + weight
    const int w    = tid >> 5;
    const int lane = tid & 31;
    const int g    = lane >> 2;
    const int t4   = lane & 3;
    const int rowA = w * 32 + g;

    auto prefetch = [&](int k, int b) {
        const uint4* src = (const uint4*)(g_Wb + k * 4096);
        #pragma unroll
        for (int it = 0; it < 2; ++it) {
            const int idx = tid + it * 256;
            cp_async16(&Ws[b * 64 * SW + (idx >> 3) * SW + (idx & 7) * 8], &src[idx]);
        }
        if (tid < 16) cp_async16(&ts[b * 64 + tid * 4], &g_t[k * 64 + tid * 4]);
    };

    prefetch(0, 0);
    asm volatile("cp.async.commit_group;\n");

    float acc = 0.f;

    for (int k = 0; k < 32; ++k) {
        const int buf = k & 1;
        __syncthreads();
        if (k + 1 < 32) prefetch(k + 1, buf ^ 1);
        asm volatile("cp.async.commit_group;\n");
        asm volatile("cp.async.wait_group 1;\n");
        __syncthreads();

        const __nv_bfloat16* Wk = Ws + buf * 64 * SW;
        const float*        tsb = ts + buf * 64;

        unsigned aA[4][4], aB[4][4];
        #pragma unroll
        for (int es = 0; es < 4; ++es) {
            const int e0 = es * 16 + 2 * t4;
            aA[es][0] = *(const unsigned*)&Xs[(rowA)      * SW + e0];
            aA[es][1] = *(const unsigned*)&Xs[(rowA +  8) * SW + e0];
            aA[es][2] = *(const unsigned*)&Xs[(rowA)      * SW + e0 + 8];
            aA[es][3] = *(const unsigned*)&Xs[(rowA +  8) * SW + e0 + 8];
            aB[es][0] = *(const unsigned*)&Xs[(rowA + 16) * SW + e0];
            aB[es][1] = *(const unsigned*)&Xs[(rowA + 24) * SW + e0];
            aB[es][2] = *(const unsigned*)&Xs[(rowA + 16) * SW + e0 + 8];
            aB[es][3] = *(const unsigned*)&Xs[(rowA + 24) * SW + e0 + 8];
        }
        const float pA0 = Ps[(rowA)      * 33 + k];
        const float pA8 = Ps[(rowA +  8) * 33 + k];
        const float pB0 = Ps[(rowA + 16) * 33 + k];
        const float pB8 = Ps[(rowA + 24) * 33 + k];

        #pragma unroll
        for (int j = 0; j < 8; ++j) {
            const float t0 = tsb[j * 8 + 2 * t4];
            const float t1 = tsb[j * 8 + 2 * t4 + 1];
            float cA0 = -t0, cA1 = -t1, cA2 = -t0, cA3 = -t1;
            float cB0 = -t0, cB1 = -t1, cB2 = -t0, cB3 = -t1;
            #pragma unroll
            for (int es = 0; es < 4; ++es) {
                const int e0 = es * 16 + 2 * t4;
                const unsigned b0v = *(const unsigned*)&Wk[(j * 8 + g) * SW + e0];
                const unsigned b1v = *(const unsigned*)&Wk[(j * 8 + g) * SW + e0 + 8];
                asm volatile(
                    "mma.sync.aligned.m16n8k16.row.col.f32.bf16.bf16.f32 "
                    "{%0,%1,%2,%3}, {%4,%5,%6,%7}, {%8,%9}, {%0,%1,%2,%3};\n"
                    : "+f"(cA0), "+f"(cA1), "+f"(cA2), "+f"(cA3)
                    : "r"(aA[es][0]), "r"(aA[es][1]), "r"(aA[es][2]), "r"(aA[es][3]),
                      "r"(b0v), "r"(b1v));
                asm volatile(
                    "mma.sync.aligned.m16n8k16.row.col.f32.bf16.bf16.f32 "
                    "{%0,%1,%2,%3}, {%4,%5,%6,%7}, {%8,%9}, {%0,%1,%2,%3};\n"
                    : "+f"(cB0), "+f"(cB1), "+f"(cB2), "+f"(cB3)
                    : "r"(aB[es][0]), "r"(aB[es][1]), "r"(aB[es][2]), "r"(aB[es][3]),
                      "r"(b0v), "r"(b1v));
            }
            acc = fmaf(pA0, fmaf(cA0, cA0, cA1 * cA1), acc);
            acc = fmaf(pA8, fmaf(cA2, cA2, cA3 * cA3), acc);
            acc = fmaf(pB0, fmaf(cB0, cB0, cB1 * cB1), acc);
            acc = fmaf(pB8, fmaf(cB2, cB2, cB3 * cB3), acc);
        }
    }
    acc *= -0.5f;

    // constant + logdet part: one thread per batch row
    {
        float c = 0.f;
        #pragma unroll
        for (int kk = 0; kk < 32; ++kk) c = fmaf(Ps[tid * 33 + kk], nhc[kk], c);
        acc += c;
    }

    // deterministic block reduction -> g_part[blockIdx.x]
    red[tid] = acc;
    __syncthreads();
    #pragma unroll
    for (int st = 128; st > 0; st >>= 1) {
        if (tid < st) red[tid] += red[tid + st];
        __syncthreads();
    }
    if (tid == 0) g_part[blockIdx.x] = red[0];

    // ---- phase 4: last block reduces all partials, writes out, resets flags
    if (tid == 0) {
        __threadfence();
        const int old = atomicAdd(&g_done, 1);
        flg[0] = (old == nb - 1) ? 1 : 0;
    }
    __syncthreads();
    if (flg[0]) {
        __threadfence();
        float a = 0.f;
        for (int i = tid; i < nb; i += 256) a += g_part[i];
        red[tid] = a;
        __syncthreads();
        #pragma unroll
        for (int st = 128; st > 0; st >>= 1) {
            if (tid < st) red[tid] += red[tid + st];
            __syncthreads();
        }
        if (tid == 0) {
            out[0] = fabsf(red[0]);
            g_done  = 0;     // reset for next graph replay
            g_ready = 0;
        }
    }
}

// ---------------- launch ----------------
extern "C" void kernel_launch(void* const* d_in, const int* in_sizes, int n_in,
                              void* d_out, int out_size)
{
    const float* emb    = (const float*)d_in[0];   // (500000, 64)
    const float* cen    = (const float*)d_in[1];   // (32, 64)
    const float* cov    = (const float*)d_in[2];   // (32, 64, 64)
    const float* pi     = (const float*)d_in[3];   // (500000, 32)
    const int*   labels = (const int*)d_in[4];     // (B,)
    const int B  = in_sizes[4];
    const int nb = B / 256;

    static int configured = 0;
    if (!configured) {
        cudaFuncSetAttribute(fused_kernel, cudaFuncAttributeMaxDynamicSharedMemorySize,
                             SMEM_TOTAL);
        configured = 1;
    }

    fused_kernel<<<nb, 256, SMEM_TOTAL>>>(emb, cen, cov, pi, labels, (float*)d_out);
}

// round 8
// speedup vs baseline: 1.1072x; 1.0452x over previous
#include <cuda_runtime.h>
#include <cuda_bf16.h>
#include <math.h>

// ---------------- device scratch (no allocations allowed) ----------------
__device__ __nv_bfloat16 g_Wb[33 * 64 * 64]; // [k][d][e]; slot 32 = U (cross)
__device__ float g_nhc[32];                  // -0.5*(D*log2pi + logdet + tau)
__device__ float g_part[4096];               // per-block partial sums
__device__ int   g_ready;                    // # components prepped
__device__ int   g_done;                     // # blocks finished

#define LOG2PI 1.8378770664093453f
#define SW 72   // bf16 smem row stride: conflict-free fragment LDS

// dynamic smem layout (bytes). Prep overlays [0, ~34KB) inside Xs region.
#define OFF_XS   0                         // bf16 [256*SW]           36864
#define OFF_WS   36864                     // bf16 [2][64*SW]         18432
#define OFF_PS   55296                     // float [256*33]          33792
#define OFF_NHC  89088                     // float [32]                128
#define OFF_LBL  89216                     // int   [256]              1024
#define OFF_RED  90240                     // float [128]               512
#define OFF_FLG  90752                     // int                        16
#define SMEM_TOTAL 90768

__device__ __forceinline__ void cp_async16(void* dst, const void* src) {
    unsigned a = (unsigned)__cvta_generic_to_shared(dst);
    asm volatile("cp.async.ca.shared.global [%0], [%1], 16;\n" :: "r"(a), "l"(src));
}

#define MMA(c0,c1,c2,c3,a0,a1,a2,a3,b0,b1)                                   \
    asm volatile(                                                            \
        "mma.sync.aligned.m16n8k16.row.col.f32.bf16.bf16.f32 "               \
        "{%0,%1,%2,%3}, {%4,%5,%6,%7}, {%8,%9}, {%0,%1,%2,%3};\n"            \
        : "+f"(c0), "+f"(c1), "+f"(c2), "+f"(c3)                             \
        : "r"(a0), "r"(a1), "r"(a2), "r"(a3), "r"(b0), "r"(b1))

// ---------------- prep (device fn, 128 threads) -------------------------------
__device__ void do_prep(int k, const float* __restrict__ cov,
                        const float* __restrict__ cen, char* smem_raw, int tid)
{
    float* A    = (float*)smem_raw;          // 64*65
    float* Li   = A  + 64 * 65;              // 64*65
    float* rd   = Li + 64 * 65;              // 64
    float* dl   = rd + 64;                   // 64
    float* tsm  = dl + 64;                   // 64

    const int l = tid & 31;

    for (int idx = tid; idx < 4096; idx += 128)
        A[(idx >> 6) * 65 + (idx & 63)] = cov[k * 4096 + idx];
    __syncthreads();

    // blocked right-looking Cholesky: 8 panels of 8 columns
    #pragma unroll 1
    for (int p = 0; p < 8; ++p) {
        const int c0 = p * 8;
        if (tid < 32) {                       // panel: warp 0, register-resident
            const int r0 = c0 + l, r1 = c0 + 32 + l;
            const bool act0 = (r0 < 64), act1 = (r1 < 64);
            float a0[8], a1[8];
            #pragma unroll
            for (int m = 0; m < 8; ++m) {
                a0[m] = act0 ? A[r0 * 65 + c0 + m] : 0.f;
                a1[m] = act1 ? A[r1 * 65 + c0 + m] : 0.f;
            }
            #pragma unroll
            for (int jj = 0; jj < 8; ++jj) {
                const float d = __shfl_sync(0xffffffffu, a0[jj], jj);
                float rs = rsqrtf(d);
                rs = rs * (1.5f - 0.5f * d * rs * rs);
                if (act0 && l >= jj) a0[jj] *= rs;
                if (act1)            a1[jj] *= rs;
                float lv[8];
                #pragma unroll
                for (int m = jj + 1; m < 8; ++m)
                    lv[m] = __shfl_sync(0xffffffffu, a0[jj], m);
                #pragma unroll
                for (int m = jj + 1; m < 8; ++m) {
                    if (act0 && l > jj) a0[m] -= a0[jj] * lv[m];
                    if (act1)           a1[m] -= a1[jj] * lv[m];
                }
            }
            #pragma unroll
            for (int m = 0; m < 8; ++m) {
                if (act0) A[r0 * 65 + c0 + m] = a0[m];
                if (act1) A[r1 * 65 + c0 + m] = a1[m];
            }
        }
        __syncthreads();
        // trailing rank-8 update, lower triangle only; 128 threads
        const int R = 56 - c0;
        if (R > 0) {
            const int rr = tid >> 1, cq = tid & 1;
            if (rr < R) {
                const int r = c0 + 8 + rr;
                float pr[8];
                #pragma unroll
                for (int m = 0; m < 8; ++m) pr[m] = A[r * 65 + c0 + m];
                for (int cc = cq; cc <= rr; cc += 2) {
                    const int c = c0 + 8 + cc;
                    float s = A[r * 65 + c];
                    #pragma unroll
                    for (int m = 0; m < 8; ++m) s -= pr[m] * A[c * 65 + c0 + m];
                    A[r * 65 + c] = s;
                }
            }
        }
        __syncthreads();
    }

    if (tid < 64) {
        const float dii = A[tid * 65 + tid];
        dl[tid] = 2.f * logf(dii);
        rd[tid] = 1.0f / dii;
    }
    __syncthreads();

    // forward substitution: 4 warps x 16 columns each
    {
        const int w = tid >> 5;
        const int r0 = l, r1 = l + 32;
        const int c0 = w * 16;
        float v0[16], v1[16];
        #pragma unroll
        for (int j = 0; j < 16; ++j) {
            v0[j] = (r0 == c0 + j) ? 1.f : 0.f;
            v1[j] = (r1 == c0 + j) ? 1.f : 0.f;
        }
        for (int m = 0; m < 64; ++m) {
            const float lr0 = (r0 > m) ? A[r0 * 65 + m] : 0.f;
            const float lr1 = (r1 > m) ? A[r1 * 65 + m] : 0.f;
            const float rdm = rd[m];
            const int   src = m & 31;
            const bool  lo  = (m < 32);
            #pragma unroll
            for (int j = 0; j < 16; ++j) {
                const float resid = lo ? v0[j] : v1[j];
                const float ym = __shfl_sync(0xffffffffu, resid, src) * rdm;
                v0[j] -= lr0 * ym;
                v1[j] -= lr1 * ym;
                if (l == src) Li[m * 65 + c0 + j] = ym;
            }
        }
    }
    __syncthreads();

    // t = Linv * c (fp32)
    if (tid < 64) {
        float tv = 0.f;
        #pragma unroll 4
        for (int e = 0; e <= tid; ++e) tv += Li[tid * 65 + e] * cen[k * 64 + e];
        tsm[tid] = tv;
    }
    __syncthreads();

    // u = Linv^T t (row k of the cross matrix, bf16); tau + logdet -> nhc
    if (tid < 64) {
        const int e = tid;
        float ue = 0.f;
        for (int d = e; d < 64; ++d) ue += Li[d * 65 + e] * tsm[d];
        g_Wb[32 * 4096 + k * 64 + e] = __float2bfloat16_rn(ue);
    }
    if (tid == 0) {
        float ld = 0.f, tau = 0.f;
        #pragma unroll 4
        for (int m = 0; m < 64; ++m) { ld += dl[m]; tau += tsm[m] * tsm[m]; }
        g_nhc[k] = -0.5f * (64.f * LOG2PI + ld + tau);
    }
    // bf16 W
    for (int idx = tid; idx < 4096; idx += 128) {
        const int d = idx >> 6, e = idx & 63;
        const float v = (e <= d) ? Li[d * 65 + e] : 0.f;
        g_Wb[k * 4096 + idx] = __float2bfloat16_rn(v);
    }
    __syncthreads();
}

// ---------------- single fused kernel -----------------------------------------
// grid = B/256, block = 128 threads (4 warps, each owns 64 batch rows)
__global__ void __launch_bounds__(128, 2) fused_kernel(const float* __restrict__ emb,
                                                       const float* __restrict__ cen,
                                                       const float* __restrict__ cov,
                                                       const float* __restrict__ pi,
                                                       const int* __restrict__ labels,
                                                       float* __restrict__ out)
{
    extern __shared__ char smem[];
    __nv_bfloat16* Xs  = (__nv_bfloat16*)(smem + OFF_XS);
    __nv_bfloat16* Ws  = (__nv_bfloat16*)(smem + OFF_WS);   // [buf][64*SW]
    float* Ps  = (float*)(smem + OFF_PS);
    float* nhc = (float*)(smem + OFF_NHC);
    int*   lbl = (int*)  (smem + OFF_LBL);
    float* red = (float*)(smem + OFF_RED);
    int*   flg = (int*)  (smem + OFF_FLG);

    const int tid = threadIdx.x;
    const int nb  = gridDim.x;
    const int b0  = blockIdx.x * 256;

    lbl[tid]       = labels[b0 + tid];
    lbl[tid + 128] = labels[b0 + tid + 128];

    // ---- phase 0: blocks < 32 prep one component each
    if (blockIdx.x < 32) {
        do_prep(blockIdx.x, cov, cen, smem, tid);
        if (tid == 0) { __threadfence(); atomicAdd(&g_ready, 1); }
    }
    __syncthreads();

    // ---- phase 1: gathers (independent of prep)
    {
        const int f4 = tid & 15, rg = tid >> 4;
        #pragma unroll 8
        for (int it = 0; it < 32; ++it) {
            const int row = rg + it * 8;
            const float4 v = *(const float4*)(emb + (size_t)lbl[row] * 64 + f4 * 4);
            __nv_bfloat162* p = (__nv_bfloat162*)&Xs[row * SW + f4 * 4];
            p[0] = __nv_bfloat162(__float2bfloat16_rn(v.x), __float2bfloat16_rn(v.y));
            p[1] = __nv_bfloat162(__float2bfloat16_rn(v.z), __float2bfloat16_rn(v.w));
        }
    }
    {
        const int f4 = tid & 7, rg = tid >> 3;
        #pragma unroll 8
        for (int it = 0; it < 16; ++it) {
            const int row = rg + it * 16;
            const float4 v = *(const float4*)(pi + (size_t)lbl[row] * 32 + f4 * 4);
            Ps[row * 33 + f4 * 4 + 0] = v.x;
            Ps[row * 33 + f4 * 4 + 1] = v.y;
            Ps[row * 33 + f4 * 4 + 2] = v.z;
            Ps[row * 33 + f4 * 4 + 3] = v.w;
        }
    }
    __syncthreads();   // Xs/Ps visible block-wide

    const int w    = tid >> 5;        // warp 0..3 -> rows w*64 .. w*64+63
    const int lane = tid & 31;
    const int g    = lane >> 2;
    const int t4   = lane & 3;
    const int base = w * 64;

    // A fragments: loaded ONCE, live across the whole k loop (64 regs)
    unsigned aF[4][4][4];
    #pragma unroll
    for (int es = 0; es < 4; ++es) {
        const int e0 = es * 16 + 2 * t4;
        #pragma unroll
        for (int rg = 0; rg < 4; ++rg) {
            const int r = base + rg * 16 + g;
            aF[es][rg][0] = *(const unsigned*)&Xs[r       * SW + e0];
            aF[es][rg][1] = *(const unsigned*)&Xs[(r + 8) * SW + e0];
            aF[es][rg][2] = *(const unsigned*)&Xs[r       * SW + e0 + 8];
            aF[es][rg][3] = *(const unsigned*)&Xs[(r + 8) * SW + e0 + 8];
        }
    }

    // ---- phase 2: wait for all components
    if (tid == 0) {
        while (atomicAdd(&g_ready, 0) < 32) { __nanosleep(100); }
    }
    __syncthreads();
    __threadfence();
    if (tid < 32) nhc[tid] = g_nhc[tid];

    auto prefetch = [&](int k, int b) {
        const uint4* src = (const uint4*)(g_Wb + k * 4096);
        #pragma unroll
        for (int it = 0; it < 4; ++it) {
            const int idx = tid + it * 128;
            cp_async16(&Ws[b * 64 * SW + (idx >> 3) * SW + (idx & 7) * 8], &src[idx]);
        }
    };

    prefetch(0, 0);
    asm volatile("cp.async.commit_group;\n");

    float acc_sq = 0.f, acc_cr = 0.f;

    #pragma unroll 1
    for (int k = 0; k < 32; ++k) {
        const int buf = k & 1;
        __syncthreads();
        prefetch(k + 1, buf ^ 1);              // k+1 <= 32 always (slot 32 = U)
        asm volatile("cp.async.commit_group;\n");
        asm volatile("cp.async.wait_group 1;\n");
        __syncthreads();

        const __nv_bfloat16* Wk = Ws + buf * 64 * SW;

        float p0[4], p1[4];
        #pragma unroll
        for (int rg = 0; rg < 4; ++rg) {
            const int r = base + rg * 16 + g;
            p0[rg] = Ps[r       * 33 + k];
            p1[rg] = Ps[(r + 8) * 33 + k];
        }

        #pragma unroll
        for (int j = 0; j < 8; ++j) {
            float c0[4], c1[4], c2[4], c3[4];
            #pragma unroll
            for (int rg = 0; rg < 4; ++rg) { c0[rg]=0.f; c1[rg]=0.f; c2[rg]=0.f; c3[rg]=0.f; }
            #pragma unroll
            for (int es = 0; es < 4; ++es) {
                const int e0 = es * 16 + 2 * t4;
                const unsigned b0v = *(const unsigned*)&Wk[(j * 8 + g) * SW + e0];
                const unsigned b1v = *(const unsigned*)&Wk[(j * 8 + g) * SW + e0 + 8];
                #pragma unroll
                for (int rg = 0; rg < 4; ++rg)
                    MMA(c0[rg], c1[rg], c2[rg], c3[rg],
                        aF[es][rg][0], aF[es][rg][1], aF[es][rg][2], aF[es][rg][3],
                        b0v, b1v);
            }
            #pragma unroll
            for (int rg = 0; rg < 4; ++rg) {
                acc_sq = fmaf(p0[rg], fmaf(c0[rg], c0[rg], c1[rg] * c1[rg]), acc_sq);
                acc_sq = fmaf(p1[rg], fmaf(c2[rg], c2[rg], c3[rg] * c3[rg]), acc_sq);
            }
        }
    }

    // ---- pseudo-iteration: cross terms  cross[b][k'] = x_b . u_k'
    asm volatile("cp.async.wait_group 0;\n");
    __syncthreads();
    {
        const __nv_bfloat16* Wu = Ws;          // buffer 0 holds slot 32
        #pragma unroll
        for (int j = 0; j < 4; ++j) {          // k' = j*8 .. j*8+7
            float c0[4], c1[4], c2[4], c3[4];
            #pragma unroll
            for (int rg = 0; rg < 4; ++rg) { c0[rg]=0.f; c1[rg]=0.f; c2[rg]=0.f; c3[rg]=0.f; }
            #pragma unroll
            for (int es = 0; es < 4; ++es) {
                const int e0 = es * 16 + 2 * t4;
                const unsigned b0v = *(const unsigned*)&Wu[(j * 8 + g) * SW + e0];
                const unsigned b1v = *(const unsigned*)&Wu[(j * 8 + g) * SW + e0 + 8];
                #pragma unroll
                for (int rg = 0; rg < 4; ++rg)
                    MMA(c0[rg], c1[rg], c2[rg], c3[rg],
                        aF[es][rg][0], aF[es][rg][1], aF[es][rg][2], aF[es][rg][3],
                        b0v, b1v);
            }
            const int k0 = j * 8 + 2 * t4;
            #pragma unroll
            for (int rg = 0; rg < 4; ++rg) {
                const int r = base + rg * 16 + g;
                acc_cr = fmaf(Ps[r       * 33 + k0],     c0[rg], acc_cr);
                acc_cr = fmaf(Ps[r       * 33 + k0 + 1], c1[rg], acc_cr);
                acc_cr = fmaf(Ps[(r + 8) * 33 + k0],     c2[rg], acc_cr);
                acc_cr = fmaf(Ps[(r + 8) * 33 + k0 + 1], c3[rg], acc_cr);
            }
        }
    }

    float acc = fmaf(-0.5f, acc_sq, acc_cr);

    // constant part: rows tid and tid+128
    {
        float c = 0.f;
        #pragma unroll
        for (int kk = 0; kk < 32; ++kk) {
            c = fmaf(Ps[tid * 33 + kk],         nhc[kk], c);
            c = fmaf(Ps[(tid + 128) * 33 + kk], nhc[kk], c);
        }
        acc += c;
    }

    // deterministic block reduction
    red[tid] = acc;
    __syncthreads();
    #pragma unroll
    for (int st = 64; st > 0; st >>= 1) {
        if (tid < st) red[tid] += red[tid + st];
        __syncthreads();
    }
    if (tid == 0) g_part[blockIdx.x] = red[0];

    // ---- last block: final reduce + reset
    if (tid == 0) {
        __threadfence();
        const int old = atomicAdd(&g_done, 1);
        flg[0] = (old == nb - 1) ? 1 : 0;
    }
    __syncthreads();
    if (flg[0]) {
        __threadfence();
        float a = 0.f;
        for (int i = tid; i < nb; i += 128) a += g_part[i];
        red[tid] = a;
        __syncthreads();
        #pragma unroll
        for (int st = 64; st > 0; st >>= 1) {
            if (tid < st) red[tid] += red[tid + st];
            __syncthreads();
        }
        if (tid == 0) {
            out[0] = fabsf(red[0]);
            g_done  = 0;
            g_ready = 0;
        }
    }
}

// ---------------- launch ----------------
extern "C" void kernel_launch(void* const* d_in, const int* in_sizes, int n_in,
                              void* d_out, int out_size)
{
    const float* emb    = (const float*)d_in[0];   // (500000, 64)
    const float* cen    = (const float*)d_in[1];   // (32, 64)
    const float* cov    = (const float*)d_in[2];   // (32, 64, 64)
    const float* pi     = (const float*)d_in[3];   // (500000, 32)
    const int*   labels = (const int*)d_in[4];     // (B,)
    const int B  = in_sizes[4];
    const int nb = B / 256;

    static int configured = 0;
    if (!configured) {
        cudaFuncSetAttribute(fused_kernel, cudaFuncAttributeMaxDynamicSharedMemorySize,
                             SMEM_TOTAL);
        configured = 1;
    }

    fused_kernel<<<nb, 128, SMEM_TOTAL>>>(emb, cen, cov, pi, labels, (float*)d_out);
}

// round 9
// speedup vs baseline: 1.1369x; 1.0268x over previous
#include <cuda_runtime.h>
#include <cuda_bf16.h>
#include <math.h>

// ---------------- device scratch (no allocations allowed) ----------------
__device__ __nv_bfloat16 g_Wb[33 * 64 * 64]; // [k][d][e]; slot 32 = U (cross)
__device__ float g_nhc[32];                  // -0.5*(D*log2pi + logdet + tau)
__device__ float g_part[4096];               // per-block partial sums
__device__ int   g_ready;                    // # components prepped
__device__ int   g_done;                     // # blocks finished

#define LOG2PI 1.8378770664093453f
#define SW 72   // bf16 smem row stride: conflict-free fragment LDS

// dynamic smem layout (bytes). Prep overlays [0, ~34KB) inside Xs region.
#define OFF_XS   0                         // bf16 [256*SW]           36864
#define OFF_WS   36864                     // bf16 [2][64*SW]         18432
#define OFF_PS   55296                     // float [256*33]          33792
#define OFF_NHC  89088                     // float [32]                128
#define OFF_LBL  89216                     // int   [256]              1024
#define OFF_RED  90240                     // float [128]               512
#define OFF_FLG  90752                     // int                        16
#define SMEM_TOTAL 90768

__device__ __forceinline__ void cp_async16(void* dst, const void* src) {
    unsigned a = (unsigned)__cvta_generic_to_shared(dst);
    asm volatile("cp.async.ca.shared.global [%0], [%1], 16;\n" :: "r"(a), "l"(src));
}

#define MMA(c0,c1,c2,c3,a0,a1,a2,a3,b0,b1)                                   \
    asm volatile(                                                            \
        "mma.sync.aligned.m16n8k16.row.col.f32.bf16.bf16.f32 "               \
        "{%0,%1,%2,%3}, {%4,%5,%6,%7}, {%8,%9}, {%0,%1,%2,%3};\n"            \
        : "+f"(c0), "+f"(c1), "+f"(c2), "+f"(c3)                             \
        : "r"(a0), "r"(a1), "r"(a2), "r"(a3), "r"(b0), "r"(b1))

// ---------------- prep (device fn, 128 threads) -------------------------------
__device__ void do_prep(int k, const float* __restrict__ cov,
                        const float* __restrict__ cen, char* smem_raw, int tid)
{
    float* A    = (float*)smem_raw;          // 64*65
    float* Li   = A  + 64 * 65;              // 64*65
    float* rd   = Li + 64 * 65;              // 64
    float* dl   = rd + 64;                   // 64
    float* tsm  = dl + 64;                   // 64

    const int l = tid & 31;

    for (int idx = tid; idx < 4096; idx += 128)
        A[(idx >> 6) * 65 + (idx & 63)] = cov[k * 4096 + idx];
    __syncthreads();

    // blocked right-looking Cholesky: 8 panels of 8 columns
    #pragma unroll 1
    for (int p = 0; p < 8; ++p) {
        const int c0 = p * 8;
        if (tid < 32) {                       // panel: warp 0, register-resident
            const int r0 = c0 + l, r1 = c0 + 32 + l;
            const bool act0 = (r0 < 64), act1 = (r1 < 64);
            float a0[8], a1[8];
            #pragma unroll
            for (int m = 0; m < 8; ++m) {
                a0[m] = act0 ? A[r0 * 65 + c0 + m] : 0.f;
                a1[m] = act1 ? A[r1 * 65 + c0 + m] : 0.f;
            }
            #pragma unroll
            for (int jj = 0; jj < 8; ++jj) {
                const float d = __shfl_sync(0xffffffffu, a0[jj], jj);
                float rs = rsqrtf(d);
                rs = rs * (1.5f - 0.5f * d * rs * rs);
                if (act0 && l >= jj) a0[jj] *= rs;
                if (act1)            a1[jj] *= rs;
                float lv[8];
                #pragma unroll
                for (int m = jj + 1; m < 8; ++m)
                    lv[m] = __shfl_sync(0xffffffffu, a0[jj], m);
                #pragma unroll
                for (int m = jj + 1; m < 8; ++m) {
                    if (act0 && l > jj) a0[m] -= a0[jj] * lv[m];
                    if (act1)           a1[m] -= a1[jj] * lv[m];
                }
            }
            #pragma unroll
            for (int m = 0; m < 8; ++m) {
                if (act0) A[r0 * 65 + c0 + m] = a0[m];
                if (act1) A[r1 * 65 + c0 + m] = a1[m];
            }
        }
        __syncthreads();
        // trailing rank-8 update, lower triangle only; 128 threads
        const int R = 56 - c0;
        if (R > 0) {
            const int rr = tid >> 1, cq = tid & 1;
            if (rr < R) {
                const int r = c0 + 8 + rr;
                float pr[8];
                #pragma unroll
                for (int m = 0; m < 8; ++m) pr[m] = A[r * 65 + c0 + m];
                for (int cc = cq; cc <= rr; cc += 2) {
                    const int c = c0 + 8 + cc;
                    float s = A[r * 65 + c];
                    #pragma unroll
                    for (int m = 0; m < 8; ++m) s -= pr[m] * A[c * 65 + c0 + m];
                    A[r * 65 + c] = s;
                }
            }
        }
        __syncthreads();
    }

    if (tid < 64) {
        const float dii = A[tid * 65 + tid];
        dl[tid] = 2.f * logf(dii);
        rd[tid] = 1.0f / dii;
    }
    __syncthreads();

    // forward substitution: 4 warps x 16 columns each
    {
        const int w = tid >> 5;
        const int r0 = l, r1 = l + 32;
        const int c0 = w * 16;
        float v0[16], v1[16];
        #pragma unroll
        for (int j = 0; j < 16; ++j) {
            v0[j] = (r0 == c0 + j) ? 1.f : 0.f;
            v1[j] = (r1 == c0 + j) ? 1.f : 0.f;
        }
        for (int m = 0; m < 64; ++m) {
            const float lr0 = (r0 > m) ? A[r0 * 65 + m] : 0.f;
            const float lr1 = (r1 > m) ? A[r1 * 65 + m] : 0.f;
            const float rdm = rd[m];
            const int   src = m & 31;
            const bool  lo  = (m < 32);
            #pragma unroll
            for (int j = 0; j < 16; ++j) {
                const float resid = lo ? v0[j] : v1[j];
                const float ym = __shfl_sync(0xffffffffu, resid, src) * rdm;
                v0[j] -= lr0 * ym;
                v1[j] -= lr1 * ym;
                if (l == src) Li[m * 65 + c0 + j] = ym;
            }
        }
    }
    __syncthreads();

    // t = Linv * c (fp32)
    if (tid < 64) {
        float tv = 0.f;
        #pragma unroll 4
        for (int e = 0; e <= tid; ++e) tv += Li[tid * 65 + e] * cen[k * 64 + e];
        tsm[tid] = tv;
    }
    __syncthreads();

    // u = Linv^T t (row k of the cross matrix, bf16); tau + logdet -> nhc
    if (tid < 64) {
        const int e = tid;
        float ue = 0.f;
        for (int d = e; d < 64; ++d) ue += Li[d * 65 + e] * tsm[d];
        g_Wb[32 * 4096 + k * 64 + e] = __float2bfloat16_rn(ue);
    }
    if (tid == 0) {
        float ld = 0.f, tau = 0.f;
        #pragma unroll 4
        for (int m = 0; m < 64; ++m) { ld += dl[m]; tau += tsm[m] * tsm[m]; }
        g_nhc[k] = -0.5f * (64.f * LOG2PI + ld + tau);
    }
    // bf16 W
    for (int idx = tid; idx < 4096; idx += 128) {
        const int d = idx >> 6, e = idx & 63;
        const float v = (e <= d) ? Li[d * 65 + e] : 0.f;
        g_Wb[k * 4096 + idx] = __float2bfloat16_rn(v);
    }
    __syncthreads();
}

// ---------------- single fused kernel -----------------------------------------
// grid = B/256, block = 128 threads (4 warps, each owns 64 batch rows)
__global__ void __launch_bounds__(128, 2) fused_kernel(const float* __restrict__ emb,
                                                       const float* __restrict__ cen,
                                                       const float* __restrict__ cov,
                                                       const float* __restrict__ pi,
                                                       const int* __restrict__ labels,
                                                       float* __restrict__ out)
{
    extern __shared__ char smem[];
    __nv_bfloat16* Xs  = (__nv_bfloat16*)(smem + OFF_XS);
    __nv_bfloat16* Ws  = (__nv_bfloat16*)(smem + OFF_WS);   // [buf][64*SW]
    float* Ps  = (float*)(smem + OFF_PS);
    float* nhc = (float*)(smem + OFF_NHC);
    int*   lbl = (int*)  (smem + OFF_LBL);
    float* red = (float*)(smem + OFF_RED);
    int*   flg = (int*)  (smem + OFF_FLG);

    const int tid = threadIdx.x;
    const int nb  = gridDim.x;
    const int b0  = blockIdx.x * 256;

    lbl[tid]       = labels[b0 + tid];
    lbl[tid + 128] = labels[b0 + tid + 128];

    // ---- phase 0: blocks < 32 prep one component each
    if (blockIdx.x < 32) {
        do_prep(blockIdx.x, cov, cen, smem, tid);
        if (tid == 0) { __threadfence(); atomicAdd(&g_ready, 1); }
    }
    __syncthreads();

    // ---- phase 1: gathers (independent of prep)
    {
        const int f4 = tid & 15, rg = tid >> 4;
        #pragma unroll 8
        for (int it = 0; it < 32; ++it) {
            const int row = rg + it * 8;
            const float4 v = *(const float4*)(emb + (size_t)lbl[row] * 64 + f4 * 4);
            __nv_bfloat162* p = (__nv_bfloat162*)&Xs[row * SW + f4 * 4];
            p[0] = __nv_bfloat162(__float2bfloat16_rn(v.x), __float2bfloat16_rn(v.y));
            p[1] = __nv_bfloat162(__float2bfloat16_rn(v.z), __float2bfloat16_rn(v.w));
        }
    }
    {
        const int f4 = tid & 7, rg = tid >> 3;
        #pragma unroll 8
        for (int it = 0; it < 16; ++it) {
            const int row = rg + it * 16;
            const float4 v = *(const float4*)(pi + (size_t)lbl[row] * 32 + f4 * 4);
            Ps[row * 33 + f4 * 4 + 0] = v.x;
            Ps[row * 33 + f4 * 4 + 1] = v.y;
            Ps[row * 33 + f4 * 4 + 2] = v.z;
            Ps[row * 33 + f4 * 4 + 3] = v.w;
        }
    }
    __syncthreads();   // Xs/Ps visible block-wide

    const int w    = tid >> 5;        // warp 0..3 -> rows w*64 .. w*64+63
    const int lane = tid & 31;
    const int g    = lane >> 2;
    const int t4   = lane & 3;
    const int base = w * 64;

    // A fragments: loaded ONCE, live across the whole k loop (64 regs)
    unsigned aF[4][4][4];
    #pragma unroll
    for (int es = 0; es < 4; ++es) {
        const int e0 = es * 16 + 2 * t4;
        #pragma unroll
        for (int rg = 0; rg < 4; ++rg) {
            const int r = base + rg * 16 + g;
            aF[es][rg][0] = *(const unsigned*)&Xs[r       * SW + e0];
            aF[es][rg][1] = *(const unsigned*)&Xs[(r + 8) * SW + e0];
            aF[es][rg][2] = *(const unsigned*)&Xs[r       * SW + e0 + 8];
            aF[es][rg][3] = *(const unsigned*)&Xs[(r + 8) * SW + e0 + 8];
        }
    }

    // ---- phase 2: wait for all components
    if (tid == 0) {
        while (atomicAdd(&g_ready, 0) < 32) { __nanosleep(100); }
    }
    __syncthreads();
    __threadfence();
    if (tid < 32) nhc[tid] = g_nhc[tid];

    auto prefetch = [&](int k, int b) {
        const uint4* src = (const uint4*)(g_Wb + k * 4096);
        #pragma unroll
        for (int it = 0; it < 4; ++it) {
            const int idx = tid + it * 128;
            cp_async16(&Ws[b * 64 * SW + (idx >> 3) * SW + (idx & 7) * 8], &src[idx]);
        }
    };

    prefetch(0, 0);
    asm volatile("cp.async.commit_group;\n");

    // 8 independent square-term accumulators (break the serial FMA chain)
    float accs[4][2];
    #pragma unroll
    for (int rg = 0; rg < 4; ++rg) { accs[rg][0] = 0.f; accs[rg][1] = 0.f; }
    // 4 independent cross-term accumulators
    float accc[4] = {0.f, 0.f, 0.f, 0.f};

    #pragma unroll 1
    for (int k = 0; k < 32; ++k) {
        const int buf = k & 1;
        __syncthreads();
        prefetch(k + 1, buf ^ 1);              // k+1 <= 32 always (slot 32 = U)
        asm volatile("cp.async.commit_group;\n");
        asm volatile("cp.async.wait_group 1;\n");
        __syncthreads();

        const __nv_bfloat16* Wk = Ws + buf * 64 * SW;

        float p0[4], p1[4];
        #pragma unroll
        for (int rg = 0; rg < 4; ++rg) {
            const int r = base + rg * 16 + g;
            p0[rg] = Ps[r       * 33 + k];
            p1[rg] = Ps[(r + 8) * 33 + k];
        }

        #pragma unroll
        for (int j = 0; j < 8; ++j) {
            float c0[4], c1[4], c2[4], c3[4];
            #pragma unroll
            for (int rg = 0; rg < 4; ++rg) { c0[rg]=0.f; c1[rg]=0.f; c2[rg]=0.f; c3[rg]=0.f; }
            #pragma unroll
            for (int es = 0; es < 4; ++es) {
                const int e0 = es * 16 + 2 * t4;
                const unsigned b0v = *(const unsigned*)&Wk[(j * 8 + g) * SW + e0];
                const unsigned b1v = *(const unsigned*)&Wk[(j * 8 + g) * SW + e0 + 8];
                #pragma unroll
                for (int rg = 0; rg < 4; ++rg)
                    MMA(c0[rg], c1[rg], c2[rg], c3[rg],
                        aF[es][rg][0], aF[es][rg][1], aF[es][rg][2], aF[es][rg][3],
                        b0v, b1v);
            }
            #pragma unroll
            for (int rg = 0; rg < 4; ++rg) {
                accs[rg][0] = fmaf(p0[rg], fmaf(c0[rg], c0[rg], c1[rg] * c1[rg]), accs[rg][0]);
                accs[rg][1] = fmaf(p1[rg], fmaf(c2[rg], c2[rg], c3[rg] * c3[rg]), accs[rg][1]);
            }
        }
    }

    // ---- pseudo-iteration: cross terms  cross[b][k'] = x_b . u_k'
    asm volatile("cp.async.wait_group 0;\n");
    __syncthreads();
    {
        const __nv_bfloat16* Wu = Ws;          // buffer 0 holds slot 32
        #pragma unroll
        for (int j = 0; j < 4; ++j) {          // k' = j*8 .. j*8+7
            float c0[4], c1[4], c2[4], c3[4];
            #pragma unroll
            for (int rg = 0; rg < 4; ++rg) { c0[rg]=0.f; c1[rg]=0.f; c2[rg]=0.f; c3[rg]=0.f; }
            #pragma unroll
            for (int es = 0; es < 4; ++es) {
                const int e0 = es * 16 + 2 * t4;
                const unsigned b0v = *(const unsigned*)&Wu[(j * 8 + g) * SW + e0];
                const unsigned b1v = *(const unsigned*)&Wu[(j * 8 + g) * SW + e0 + 8];
                #pragma unroll
                for (int rg = 0; rg < 4; ++rg)
                    MMA(c0[rg], c1[rg], c2[rg], c3[rg],
                        aF[es][rg][0], aF[es][rg][1], aF[es][rg][2], aF[es][rg][3],
                        b0v, b1v);
            }
            const int k0 = j * 8 + 2 * t4;
            #pragma unroll
            for (int rg = 0; rg < 4; ++rg) {
                const int r = base + rg * 16 + g;
                float cc;
                cc = fmaf(Ps[r       * 33 + k0],     c0[rg],
                     fmaf(Ps[r       * 33 + k0 + 1], c1[rg], 0.f));
                cc = fmaf(Ps[(r + 8) * 33 + k0],     c2[rg], cc);
                cc = fmaf(Ps[(r + 8) * 33 + k0 + 1], c3[rg], cc);
                accc[rg] += cc;
            }
        }
    }

    // deterministic combine of private partials
    float acc_sq = ((accs[0][0] + accs[0][1]) + (accs[1][0] + accs[1][1]))
                 + ((accs[2][0] + accs[2][1]) + (accs[3][0] + accs[3][1]));
    float acc_cr = (accc[0] + accc[1]) + (accc[2] + accc[3]);
    float acc = fmaf(-0.5f, acc_sq, acc_cr);

    // constant part: rows tid and tid+128
    {
        float c = 0.f;
        #pragma unroll
        for (int kk = 0; kk < 32; ++kk) {
            c = fmaf(Ps[tid * 33 + kk],         nhc[kk], c);
            c = fmaf(Ps[(tid + 128) * 33 + kk], nhc[kk], c);
        }
        acc += c;
    }

    // deterministic block reduction
    red[tid] = acc;
    __syncthreads();
    #pragma unroll
    for (int st = 64; st > 0; st >>= 1) {
        if (tid < st) red[tid] += red[tid + st];
        __syncthreads();
    }
    if (tid == 0) g_part[blockIdx.x] = red[0];

    // ---- last block: final reduce + reset
    if (tid == 0) {
        __threadfence();
        const int old = atomicAdd(&g_done, 1);
        flg[0] = (old == nb - 1) ? 1 : 0;
    }
    __syncthreads();
    if (flg[0]) {
        __threadfence();
        float a = 0.f;
        for (int i = tid; i < nb; i += 128) a += g_part[i];
        red[tid] = a;
        __syncthreads();
        #pragma unroll
        for (int st = 64; st > 0; st >>= 1) {
            if (tid < st) red[tid] += red[tid + st];
            __syncthreads();
        }
        if (tid == 0) {
            out[0] = fabsf(red[0]);
            g_done  = 0;
            g_ready = 0;
        }
    }
}

// ---------------- launch ----------------
extern "C" void kernel_launch(void* const* d_in, const int* in_sizes, int n_in,
                              void* d_out, int out_size)
{
    const float* emb    = (const float*)d_in[0];   // (500000, 64)
    const float* cen    = (const float*)d_in[1];   // (32, 64)
    const float* cov    = (const float*)d_in[2];   // (32, 64, 64)
    const float* pi     = (const float*)d_in[3];   // (500000, 32)
    const int*   labels = (const int*)d_in[4];     // (B,)
    const int B  = in_sizes[4];
    const int nb = B / 256;

    static int configured = 0;
    if (!configured) {
        cudaFuncSetAttribute(fused_kernel, cudaFuncAttributeMaxDynamicSharedMemorySize,
                             SMEM_TOTAL);
        configured = 1;
    }

    fused_kernel<<<nb, 128, SMEM_TOTAL>>>(emb, cen, cov, pi, labels, (float*)d_out);
}

// round 10
// speedup vs baseline: 1.3766x; 1.2109x over previous
#include <cuda_runtime.h>
#include <cuda_bf16.h>
#include <math.h>

// ---------------- device scratch (no allocations allowed) ----------------
__device__ __nv_bfloat16 g_Wb[33 * 64 * 64]; // [k][d][e]; slot 32 = U (cross)
__device__ float g_nhc[32];                  // -0.5*(D*log2pi + logdet + tau)
__device__ float g_part[4096];               // per-block partial sums
__device__ int   g_ready;                    // # components prepped
__device__ int   g_done;                     // # blocks finished

#define LOG2PI 1.8378770664093453f
#define SW 72   // bf16 smem row stride: conflict-free fragment LDS

// dynamic smem layout (bytes). Prep overlays [0, ~34KB) inside Xs region.
#define OFF_XS   0                         // bf16 [256*SW]           36864
#define OFF_WS   36864                     // bf16 [2][64*SW]         18432
#define OFF_PS   55296                     // float [256*33]          33792
#define OFF_NHC  89088                     // float [32]                128
#define OFF_LBL  89216                     // int   [256]              1024
#define OFF_RED  90240                     // float [128]               512
#define OFF_FLG  90752                     // int                        16
#define SMEM_TOTAL 90768

__device__ __forceinline__ void cp_async16(void* dst, const void* src) {
    unsigned a = (unsigned)__cvta_generic_to_shared(dst);
    asm volatile("cp.async.ca.shared.global [%0], [%1], 16;\n" :: "r"(a), "l"(src));
}

#define MMA(c0,c1,c2,c3,a0,a1,a2,a3,b0,b1)                                   \
    asm volatile(                                                            \
        "mma.sync.aligned.m16n8k16.row.col.f32.bf16.bf16.f32 "               \
        "{%0,%1,%2,%3}, {%4,%5,%6,%7}, {%8,%9}, {%0,%1,%2,%3};\n"            \
        : "+f"(c0), "+f"(c1), "+f"(c2), "+f"(c3)                             \
        : "r"(a0), "r"(a1), "r"(a2), "r"(a3), "r"(b0), "r"(b1))

// ---------------- prep (device fn, 128 threads) -------------------------------
__device__ void do_prep(int k, const float* __restrict__ cov,
                        const float* __restrict__ cen, char* smem_raw, int tid)
{
    float* A    = (float*)smem_raw;          // 64*65
    float* Li   = A  + 64 * 65;              // 64*65
    float* rd   = Li + 64 * 65;              // 64
    float* dl   = rd + 64;                   // 64
    float* tsm  = dl + 64;                   // 64

    const int l = tid & 31;

    for (int idx = tid; idx < 4096; idx += 128)
        A[(idx >> 6) * 65 + (idx & 63)] = cov[k * 4096 + idx];
    __syncthreads();

    // blocked right-looking Cholesky: 8 panels of 8 columns
    #pragma unroll 1
    for (int p = 0; p < 8; ++p) {
        const int c0 = p * 8;
        if (tid < 32) {                       // panel: warp 0, register-resident
            const int r0 = c0 + l, r1 = c0 + 32 + l;
            const bool act0 = (r0 < 64), act1 = (r1 < 64);
            float a0[8], a1[8];
            #pragma unroll
            for (int m = 0; m < 8; ++m) {
                a0[m] = act0 ? A[r0 * 65 + c0 + m] : 0.f;
                a1[m] = act1 ? A[r1 * 65 + c0 + m] : 0.f;
            }
            #pragma unroll
            for (int jj = 0; jj < 8; ++jj) {
                const float d = __shfl_sync(0xffffffffu, a0[jj], jj);
                const float rs = rsqrtf(d);   // ~2 ulp: plenty vs 1e-3 threshold
                if (act0 && l >= jj) a0[jj] *= rs;
                if (act1)            a1[jj] *= rs;
                float lv[8];
                #pragma unroll
                for (int m = jj + 1; m < 8; ++m)
                    lv[m] = __shfl_sync(0xffffffffu, a0[jj], m);
                #pragma unroll
                for (int m = jj + 1; m < 8; ++m) {
                    if (act0 && l > jj) a0[m] -= a0[jj] * lv[m];
                    if (act1)           a1[m] -= a1[jj] * lv[m];
                }
            }
            #pragma unroll
            for (int m = 0; m < 8; ++m) {
                if (act0) A[r0 * 65 + c0 + m] = a0[m];
                if (act1) A[r1 * 65 + c0 + m] = a1[m];
            }
        }
        __syncthreads();
        // trailing rank-8 update, lower triangle only; 128 threads
        const int R = 56 - c0;
        if (R > 0) {
            const int rr = tid >> 1, cq = tid & 1;
            if (rr < R) {
                const int r = c0 + 8 + rr;
                float pr[8];
                #pragma unroll
                for (int m = 0; m < 8; ++m) pr[m] = A[r * 65 + c0 + m];
                for (int cc = cq; cc <= rr; cc += 2) {
                    const int c = c0 + 8 + cc;
                    float s = A[r * 65 + c];
                    #pragma unroll
                    for (int m = 0; m < 8; ++m) s -= pr[m] * A[c * 65 + c0 + m];
                    A[r * 65 + c] = s;
                }
            }
        }
        __syncthreads();
    }

    if (tid < 64) {
        const float dii = A[tid * 65 + tid];
        dl[tid] = 2.f * logf(dii);
        rd[tid] = 1.0f / dii;
    }
    __syncthreads();

    // forward substitution: 4 warps x 16 columns each
    {
        const int w = tid >> 5;
        const int r0 = l, r1 = l + 32;
        const int c0 = w * 16;
        float v0[16], v1[16];
        #pragma unroll
        for (int j = 0; j < 16; ++j) {
            v0[j] = (r0 == c0 + j) ? 1.f : 0.f;
            v1[j] = (r1 == c0 + j) ? 1.f : 0.f;
        }
        for (int m = 0; m < 64; ++m) {
            const float lr0 = (r0 > m) ? A[r0 * 65 + m] : 0.f;
            const float lr1 = (r1 > m) ? A[r1 * 65 + m] : 0.f;
            const float rdm = rd[m];
            const int   src = m & 31;
            const bool  lo  = (m < 32);
            #pragma unroll
            for (int j = 0; j < 16; ++j) {
                const float resid = lo ? v0[j] : v1[j];
                const float ym = __shfl_sync(0xffffffffu, resid, src) * rdm;
                v0[j] -= lr0 * ym;
                v1[j] -= lr1 * ym;
                if (l == src) Li[m * 65 + c0 + j] = ym;
            }
        }
    }
    __syncthreads();

    // t = Linv * c (fp32)
    if (tid < 64) {
        float tv = 0.f;
        #pragma unroll 4
        for (int e = 0; e <= tid; ++e) tv += Li[tid * 65 + e] * cen[k * 64 + e];
        tsm[tid] = tv;
    }
    __syncthreads();

    // u = Linv^T t (row k of the cross matrix, bf16); tau + logdet -> nhc
    if (tid < 64) {
        const int e = tid;
        float ue = 0.f;
        for (int d = e; d < 64; ++d) ue += Li[d * 65 + e] * tsm[d];
        g_Wb[32 * 4096 + k * 64 + e] = __float2bfloat16_rn(ue);
    }
    if (tid == 0) {
        float ld = 0.f, tau = 0.f;
        #pragma unroll 4
        for (int m = 0; m < 64; ++m) { ld += dl[m]; tau += tsm[m] * tsm[m]; }
        g_nhc[k] = -0.5f * (64.f * LOG2PI + ld + tau);
    }
    // bf16 W
    for (int idx = tid; idx < 4096; idx += 128) {
        const int d = idx >> 6, e = idx & 63;
        const float v = (e <= d) ? Li[d * 65 + e] : 0.f;
        g_Wb[k * 4096 + idx] = __float2bfloat16_rn(v);
    }
    __syncthreads();
}

// ---------------- single fused kernel -----------------------------------------
// grid = B/256, block = 128 threads (4 warps, each owns 64 batch rows)
__global__ void __launch_bounds__(128, 2) fused_kernel(const float* __restrict__ emb,
                                                       const float* __restrict__ cen,
                                                       const float* __restrict__ cov,
                                                       const float* __restrict__ pi,
                                                       const int* __restrict__ labels,
                                                       float* __restrict__ out)
{
    extern __shared__ char smem[];
    __nv_bfloat16* Xs  = (__nv_bfloat16*)(smem + OFF_XS);
    __nv_bfloat16* Ws  = (__nv_bfloat16*)(smem + OFF_WS);   // [buf][64*SW]
    float* Ps  = (float*)(smem + OFF_PS);
    float* nhc = (float*)(smem + OFF_NHC);
    int*   lbl = (int*)  (smem + OFF_LBL);
    float* red = (float*)(smem + OFF_RED);
    int*   flg = (int*)  (smem + OFF_FLG);

    const int tid = threadIdx.x;
    const int nb  = gridDim.x;
    const int b0  = blockIdx.x * 256;

    lbl[tid]       = labels[b0 + tid];
    lbl[tid + 128] = labels[b0 + tid + 128];

    // ---- phase 0: blocks < 32 prep one component each
    if (blockIdx.x < 32) {
        do_prep(blockIdx.x, cov, cen, smem, tid);
        if (tid == 0) { __threadfence(); atomicAdd(&g_ready, 1); }
    }
    __syncthreads();

    // ---- phase 1: gathers (independent of prep)
    {
        const int f4 = tid & 15, rg = tid >> 4;
        #pragma unroll 8
        for (int it = 0; it < 32; ++it) {
            const int row = rg + it * 8;
            const float4 v = *(const float4*)(emb + (size_t)lbl[row] * 64 + f4 * 4);
            __nv_bfloat162* p = (__nv_bfloat162*)&Xs[row * SW + f4 * 4];
            p[0] = __nv_bfloat162(__float2bfloat16_rn(v.x), __float2bfloat16_rn(v.y));
            p[1] = __nv_bfloat162(__float2bfloat16_rn(v.z), __float2bfloat16_rn(v.w));
        }
    }
    {
        const int f4 = tid & 7, rg = tid >> 3;
        #pragma unroll 8
        for (int it = 0; it < 16; ++it) {
            const int row = rg + it * 16;
            const float4 v = *(const float4*)(pi + (size_t)lbl[row] * 32 + f4 * 4);
            Ps[row * 33 + f4 * 4 + 0] = v.x;
            Ps[row * 33 + f4 * 4 + 1] = v.y;
            Ps[row * 33 + f4 * 4 + 2] = v.z;
            Ps[row * 33 + f4 * 4 + 3] = v.w;
        }
    }
    __syncthreads();   // Xs/Ps visible block-wide

    const int w    = tid >> 5;        // warp 0..3 -> rows w*64 .. w*64+63
    const int lane = tid & 31;
    const int g    = lane >> 2;
    const int t4   = lane & 3;
    const int base = w * 64;

    // A fragments: loaded ONCE, live across the whole k loop (64 regs)
    unsigned aF[4][4][4];
    #pragma unroll
    for (int es = 0; es < 4; ++es) {
        const int e0 = es * 16 + 2 * t4;
        #pragma unroll
        for (int rg = 0; rg < 4; ++rg) {
            const int r = base + rg * 16 + g;
            aF[es][rg][0] = *(const unsigned*)&Xs[r       * SW + e0];
            aF[es][rg][1] = *(const unsigned*)&Xs[(r + 8) * SW + e0];
            aF[es][rg][2] = *(const unsigned*)&Xs[r       * SW + e0 + 8];
            aF[es][rg][3] = *(const unsigned*)&Xs[(r + 8) * SW + e0 + 8];
        }
    }

    // ---- phase 2: wait for all components
    if (tid == 0) {
        while (atomicAdd(&g_ready, 0) < 32) { __nanosleep(100); }
    }
    __syncthreads();
    __threadfence();
    if (tid < 32) nhc[tid] = g_nhc[tid];

    auto prefetch = [&](int k, int b) {
        const uint4* src = (const uint4*)(g_Wb + k * 4096);
        #pragma unroll
        for (int it = 0; it < 4; ++it) {
            const int idx = tid + it * 128;
            cp_async16(&Ws[b * 64 * SW + (idx >> 3) * SW + (idx & 7) * 8], &src[idx]);
        }
    };

    prefetch(0, 0);
    asm volatile("cp.async.commit_group;\n");

    // 8 independent square-term accumulators
    float accs[4][2];
    #pragma unroll
    for (int rg = 0; rg < 4; ++rg) { accs[rg][0] = 0.f; accs[rg][1] = 0.f; }
    float accc[4] = {0.f, 0.f, 0.f, 0.f};

    #pragma unroll 1
    for (int k = 0; k < 32; ++k) {
        const int buf = k & 1;
        __syncthreads();
        prefetch(k + 1, buf ^ 1);              // k+1 <= 32 always (slot 32 = U)
        asm volatile("cp.async.commit_group;\n");
        asm volatile("cp.async.wait_group 1;\n");
        __syncthreads();

        const __nv_bfloat16* Wk = Ws + buf * 64 * SW;

        float p0[4], p1[4];
        #pragma unroll
        for (int rg = 0; rg < 4; ++rg) {
            const int r = base + rg * 16 + g;
            p0[rg] = Ps[r       * 33 + k];
            p1[rg] = Ps[(r + 8) * 33 + k];
        }

        #pragma unroll
        for (int j = 0; j < 8; ++j) {
            float c0[4], c1[4], c2[4], c3[4];
            #pragma unroll
            for (int rg = 0; rg < 4; ++rg) { c0[rg]=0.f; c1[rg]=0.f; c2[rg]=0.f; c3[rg]=0.f; }
            // lower-triangular W: rows d in [8j, 8j+8) need only e <= 8j+7
            // -> only the first j/2+1 of the 4 es-blocks are nonzero (EXACT skip)
            const int esn = j / 2 + 1;
            #pragma unroll
            for (int es = 0; es < esn; ++es) {
                const int e0 = es * 16 + 2 * t4;
                const unsigned b0v = *(const unsigned*)&Wk[(j * 8 + g) * SW + e0];
                const unsigned b1v = *(const unsigned*)&Wk[(j * 8 + g) * SW + e0 + 8];
                #pragma unroll
                for (int rg = 0; rg < 4; ++rg)
                    MMA(c0[rg], c1[rg], c2[rg], c3[rg],
                        aF[es][rg][0], aF[es][rg][1], aF[es][rg][2], aF[es][rg][3],
                        b0v, b1v);
            }
            #pragma unroll
            for (int rg = 0; rg < 4; ++rg) {
                accs[rg][0] = fmaf(p0[rg], fmaf(c0[rg], c0[rg], c1[rg] * c1[rg]), accs[rg][0]);
                accs[rg][1] = fmaf(p1[rg], fmaf(c2[rg], c2[rg], c3[rg] * c3[rg]), accs[rg][1]);
            }
        }
    }

    // ---- pseudo-iteration: cross terms  cross[b][k'] = x_b . u_k'  (U dense!)
    asm volatile("cp.async.wait_group 0;\n");
    __syncthreads();
    {
        const __nv_bfloat16* Wu = Ws;          // buffer 0 holds slot 32
        #pragma unroll
        for (int j = 0; j < 4; ++j) {          // k' = j*8 .. j*8+7
            float c0[4], c1[4], c2[4], c3[4];
            #pragma unroll
            for (int rg = 0; rg < 4; ++rg) { c0[rg]=0.f; c1[rg]=0.f; c2[rg]=0.f; c3[rg]=0.f; }
            #pragma unroll
            for (int es = 0; es < 4; ++es) {
                const int e0 = es * 16 + 2 * t4;
                const unsigned b0v = *(const unsigned*)&Wu[(j * 8 + g) * SW + e0];
                const unsigned b1v = *(const unsigned*)&Wu[(j * 8 + g) * SW + e0 + 8];
                #pragma unroll
                for (int rg = 0; rg < 4; ++rg)
                    MMA(c0[rg], c1[rg], c2[rg], c3[rg],
                        aF[es][rg][0], aF[es][rg][1], aF[es][rg][2], aF[es][rg][3],
                        b0v, b1v);
            }
            const int k0 = j * 8 + 2 * t4;
            #pragma unroll
            for (int rg = 0; rg < 4; ++rg) {
                const int r = base + rg * 16 + g;
                float cc;
                cc = fmaf(Ps[r       * 33 + k0],     c0[rg],
                     fmaf(Ps[r       * 33 + k0 + 1], c1[rg], 0.f));
                cc = fmaf(Ps[(r + 8) * 33 + k0],     c2[rg], cc);
                cc = fmaf(Ps[(r + 8) * 33 + k0 + 1], c3[rg], cc);
                accc[rg] += cc;
            }
        }
    }

    // deterministic combine of private partials
    float acc_sq = ((accs[0][0] + accs[0][1]) + (accs[1][0] + accs[1][1]))
                 + ((accs[2][0] + accs[2][1]) + (accs[3][0] + accs[3][1]));
    float acc_cr = (accc[0] + accc[1]) + (accc[2] + accc[3]);
    float acc = fmaf(-0.5f, acc_sq, acc_cr);

    // constant part: rows tid and tid+128
    {
        float c = 0.f;
        #pragma unroll
        for (int kk = 0; kk < 32; ++kk) {
            c = fmaf(Ps[tid * 33 + kk],         nhc[kk], c);
            c = fmaf(Ps[(tid + 128) * 33 + kk], nhc[kk], c);
        }
        acc += c;
    }

    // deterministic block reduction
    red[tid] = acc;
    __syncthreads();
    #pragma unroll
    for (int st = 64; st > 0; st >>= 1) {
        if (tid < st) red[tid] += red[tid + st];
        __syncthreads();
    }
    if (tid == 0) g_part[blockIdx.x] = red[0];

    // ---- last block: final reduce + reset
    if (tid == 0) {
        __threadfence();
        const int old = atomicAdd(&g_done, 1);
        flg[0] = (old == nb - 1) ? 1 : 0;
    }
    __syncthreads();
    if (flg[0]) {
        __threadfence();
        float a = 0.f;
        for (int i = tid; i < nb; i += 128) a += g_part[i];
        red[tid] = a;
        __syncthreads();
        #pragma unroll
        for (int st = 64; st > 0; st >>= 1) {
            if (tid < st) red[tid] += red[tid + st];
            __syncthreads();
        }
        if (tid == 0) {
            out[0] = fabsf(red[0]);
            g_done  = 0;
            g_ready = 0;
        }
    }
}

// ---------------- launch ----------------
extern "C" void kernel_launch(void* const* d_in, const int* in_sizes, int n_in,
                              void* d_out, int out_size)
{
    const float* emb    = (const float*)d_in[0];   // (500000, 64)
    const float* cen    = (const float*)d_in[1];   // (32, 64)
    const float* cov    = (const float*)d_in[2];   // (32, 64, 64)
    const float* pi     = (const float*)d_in[3];   // (500000, 32)
    const int*   labels = (const int*)d_in[4];     // (B,)
    const int B  = in_sizes[4];
    const int nb = B / 256;

    static int configured = 0;
    if (!configured) {
        cudaFuncSetAttribute(fused_kernel, cudaFuncAttributeMaxDynamicSharedMemorySize,
                             SMEM_TOTAL);
        configured = 1;
    }

    fused_kernel<<<nb, 128, SMEM_TOTAL>>>(emb, cen, cov, pi, labels, (float*)d_out);
}

// round 11
// speedup vs baseline: 1.3847x; 1.0059x over previous
#include <cuda_runtime.h>
#include <cuda_bf16.h>
#include <math.h>

// ---------------- device scratch (no allocations allowed) ----------------
__device__ __nv_bfloat16 g_Wb[33 * 64 * 64]; // [k][d][e]; slot 32 = U (cross)
__device__ float g_nhc[32];                  // -0.5*(D*log2pi + logdet + tau)
__device__ float g_part[4096];               // per-block partial sums
__device__ int   g_ready;                    // # components prepped
__device__ int   g_done;                     // # blocks finished

#define LOG2PI 1.8378770664093453f
#define SW 72   // bf16 smem row stride: conflict-free fragment LDS

// dynamic smem layout (bytes). Prep overlays [0, ~34KB) inside Xs region.
#define OFF_XS   0                         // bf16 [256*SW]           36864
#define OFF_WS   36864                     // bf16 [2][64*SW]         18432
#define OFF_PS   55296                     // float [256*33]          33792
#define OFF_NHC  89088                     // float [32]                128
#define OFF_LBL  89216                     // int   [256]              1024
#define OFF_RED  90240                     // float [128]               512
#define OFF_FLG  90752                     // int                        16
#define SMEM_TOTAL 90768

__device__ __forceinline__ void cp_async16(void* dst, const void* src) {
    unsigned a = (unsigned)__cvta_generic_to_shared(dst);
    asm volatile("cp.async.ca.shared.global [%0], [%1], 16;\n" :: "r"(a), "l"(src));
}

#define MMA(c0,c1,c2,c3,a0,a1,a2,a3,b0,b1)                                   \
    asm volatile(                                                            \
        "mma.sync.aligned.m16n8k16.row.col.f32.bf16.bf16.f32 "               \
        "{%0,%1,%2,%3}, {%4,%5,%6,%7}, {%8,%9}, {%0,%1,%2,%3};\n"            \
        : "+f"(c0), "+f"(c1), "+f"(c2), "+f"(c3)                             \
        : "r"(a0), "r"(a1), "r"(a2), "r"(a3), "r"(b0), "r"(b1))

// ---------------- prep (device fn, 128 threads) -------------------------------
__device__ void do_prep(int k, const float* __restrict__ cov,
                        const float* __restrict__ cen, char* smem_raw, int tid)
{
    float* A    = (float*)smem_raw;          // 64*65
    float* Li   = A  + 64 * 65;              // 64*65
    float* rd   = Li + 64 * 65;              // 64
    float* dl   = rd + 64;                   // 64
    float* tsm  = dl + 64;                   // 64

    const int l = tid & 31;

    for (int idx = tid; idx < 4096; idx += 128)
        A[(idx >> 6) * 65 + (idx & 63)] = cov[k * 4096 + idx];
    __syncthreads();

    // blocked right-looking Cholesky: 8 panels of 8 columns
    #pragma unroll 1
    for (int p = 0; p < 8; ++p) {
        const int c0 = p * 8;
        if (tid < 32) {                       // panel: warp 0, register-resident
            const int r0 = c0 + l, r1 = c0 + 32 + l;
            const bool act0 = (r0 < 64), act1 = (r1 < 64);
            float a0[8], a1[8];
            #pragma unroll
            for (int m = 0; m < 8; ++m) {
                a0[m] = act0 ? A[r0 * 65 + c0 + m] : 0.f;
                a1[m] = act1 ? A[r1 * 65 + c0 + m] : 0.f;
            }
            #pragma unroll
            for (int jj = 0; jj < 8; ++jj) {
                const float d = __shfl_sync(0xffffffffu, a0[jj], jj);
                const float rs = rsqrtf(d);
                if (act0 && l >= jj) a0[jj] *= rs;
                if (act1)            a1[jj] *= rs;
                float lv[8];
                #pragma unroll
                for (int m = jj + 1; m < 8; ++m)
                    lv[m] = __shfl_sync(0xffffffffu, a0[jj], m);
                #pragma unroll
                for (int m = jj + 1; m < 8; ++m) {
                    if (act0 && l > jj) a0[m] -= a0[jj] * lv[m];
                    if (act1)           a1[m] -= a1[jj] * lv[m];
                }
            }
            #pragma unroll
            for (int m = 0; m < 8; ++m) {
                if (act0) A[r0 * 65 + c0 + m] = a0[m];
                if (act1) A[r1 * 65 + c0 + m] = a1[m];
            }
        }
        __syncthreads();
        // trailing rank-8 update, lower triangle only; 128 threads.
        // split the 8-FMA chain into 2 independent halves.
        const int R = 56 - c0;
        if (R > 0) {
            const int rr = tid >> 1, cq = tid & 1;
            if (rr < R) {
                const int r = c0 + 8 + rr;
                float pr[8];
                #pragma unroll
                for (int m = 0; m < 8; ++m) pr[m] = A[r * 65 + c0 + m];
                #pragma unroll 4
                for (int cc = cq; cc <= rr; cc += 2) {
                    const int c = c0 + 8 + cc;
                    float s0 = A[r * 65 + c], s1 = 0.f;
                    #pragma unroll
                    for (int m = 0; m < 4; ++m) {
                        s0 -= pr[m]     * A[c * 65 + c0 + m];
                        s1 += pr[m + 4] * A[c * 65 + c0 + m + 4];
                    }
                    A[r * 65 + c] = s0 - s1;
                }
            }
        }
        __syncthreads();
    }

    if (tid < 64) {
        const float dii = A[tid * 65 + tid];
        dl[tid] = 2.f * logf(dii);
        rd[tid] = 1.0f / dii;
    }
    __syncthreads();

    // forward substitution: 4 warps x 16 columns each
    {
        const int w = tid >> 5;
        const int r0 = l, r1 = l + 32;
        const int c0 = w * 16;
        float v0[16], v1[16];
        #pragma unroll
        for (int j = 0; j < 16; ++j) {
            v0[j] = (r0 == c0 + j) ? 1.f : 0.f;
            v1[j] = (r1 == c0 + j) ? 1.f : 0.f;
        }
        for (int m = 0; m < 64; ++m) {
            const float lr0 = (r0 > m) ? A[r0 * 65 + m] : 0.f;
            const float lr1 = (r1 > m) ? A[r1 * 65 + m] : 0.f;
            const float rdm = rd[m];
            const int   src = m & 31;
            const bool  lo  = (m < 32);
            #pragma unroll
            for (int j = 0; j < 16; ++j) {
                const float resid = lo ? v0[j] : v1[j];
                const float ym = __shfl_sync(0xffffffffu, resid, src) * rdm;
                v0[j] -= lr0 * ym;
                v1[j] -= lr1 * ym;
                if (l == src) Li[m * 65 + c0 + j] = ym;
            }
        }
    }
    __syncthreads();

    // t = Linv * c (fp32), 4-way partials
    if (tid < 64) {
        float s0 = 0.f, s1 = 0.f, s2 = 0.f, s3 = 0.f;
        int e = 0;
        for (; e + 3 <= tid; e += 4) {
            s0 += Li[tid * 65 + e]     * cen[k * 64 + e];
            s1 += Li[tid * 65 + e + 1] * cen[k * 64 + e + 1];
            s2 += Li[tid * 65 + e + 2] * cen[k * 64 + e + 2];
            s3 += Li[tid * 65 + e + 3] * cen[k * 64 + e + 3];
        }
        for (; e <= tid; ++e) s0 += Li[tid * 65 + e] * cen[k * 64 + e];
        tsm[tid] = (s0 + s1) + (s2 + s3);
    }
    __syncthreads();

    // u = Linv^T t (row k of the cross matrix, bf16), 4-way partials
    if (tid < 64) {
        const int e = tid;
        float s0 = 0.f, s1 = 0.f, s2 = 0.f, s3 = 0.f;
        int d = e;
        for (; d + 3 < 64; d += 4) {
            s0 += Li[d * 65 + e]       * tsm[d];
            s1 += Li[(d + 1) * 65 + e] * tsm[d + 1];
            s2 += Li[(d + 2) * 65 + e] * tsm[d + 2];
            s3 += Li[(d + 3) * 65 + e] * tsm[d + 3];
        }
        for (; d < 64; ++d) s0 += Li[d * 65 + e] * tsm[d];
        g_Wb[32 * 4096 + k * 64 + e] = __float2bfloat16_rn((s0 + s1) + (s2 + s3));
    }
    if (tid == 0) {
        float ld = 0.f, tau = 0.f;
        #pragma unroll 4
        for (int m = 0; m < 64; ++m) { ld += dl[m]; tau += tsm[m] * tsm[m]; }
        g_nhc[k] = -0.5f * (64.f * LOG2PI + ld + tau);
    }
    // bf16 W
    #pragma unroll 4
    for (int idx = tid; idx < 4096; idx += 128) {
        const int d = idx >> 6, e = idx & 63;
        const float v = (e <= d) ? Li[d * 65 + e] : 0.f;
        g_Wb[k * 4096 + idx] = __float2bfloat16_rn(v);
    }
}

// ---------------- single fused kernel -----------------------------------------
// grid = 32 prep blocks + B/256 GEMM blocks; block = 128 threads
__global__ void __launch_bounds__(128, 2) fused_kernel(const float* __restrict__ emb,
                                                       const float* __restrict__ cen,
                                                       const float* __restrict__ cov,
                                                       const float* __restrict__ pi,
                                                       const int* __restrict__ labels,
                                                       float* __restrict__ out)
{
    extern __shared__ char smem[];
    __nv_bfloat16* Xs  = (__nv_bfloat16*)(smem + OFF_XS);
    __nv_bfloat16* Ws  = (__nv_bfloat16*)(smem + OFF_WS);   // [buf][64*SW]
    float* Ps  = (float*)(smem + OFF_PS);
    float* nhc = (float*)(smem + OFF_NHC);
    int*   lbl = (int*)  (smem + OFF_LBL);
    float* red = (float*)(smem + OFF_RED);
    int*   flg = (int*)  (smem + OFF_FLG);

    const int tid   = threadIdx.x;
    const int total = gridDim.x;         // nb + 32
    const int nb    = total - 32;

    // =================== prep blocks: prep only, then exit =====================
    if (blockIdx.x < 32) {
        do_prep(blockIdx.x, cov, cen, smem, tid);
        __syncthreads();
        if (tid == 0) {
            __threadfence();
            atomicAdd(&g_ready, 1);
            __threadfence();
            const int old = atomicAdd(&g_done, 1);
            flg[0] = (old == total - 1) ? 1 : 0;
        }
        __syncthreads();
        if (flg[0]) {                    // defensive: never last in practice
            __threadfence();
            float a = 0.f;
            for (int i = tid; i < nb; i += 128) a += g_part[i];
            red[tid] = a;
            __syncthreads();
            #pragma unroll
            for (int st = 64; st > 0; st >>= 1) {
                if (tid < st) red[tid] += red[tid + st];
                __syncthreads();
            }
            if (tid == 0) { out[0] = fabsf(red[0]); g_done = 0; g_ready = 0; }
        }
        return;
    }

    // =================== GEMM blocks ==========================================
    const int gbid = blockIdx.x - 32;
    const int b0   = gbid * 256;

    lbl[tid]       = labels[b0 + tid];
    lbl[tid + 128] = labels[b0 + tid + 128];
    __syncthreads();

    // ---- gathers (overlap prep blocks' work)
    {
        const int f4 = tid & 15, rg = tid >> 4;
        #pragma unroll 8
        for (int it = 0; it < 32; ++it) {
            const int row = rg + it * 8;
            const float4 v = *(const float4*)(emb + (size_t)lbl[row] * 64 + f4 * 4);
            __nv_bfloat162* p = (__nv_bfloat162*)&Xs[row * SW + f4 * 4];
            p[0] = __nv_bfloat162(__float2bfloat16_rn(v.x), __float2bfloat16_rn(v.y));
            p[1] = __nv_bfloat162(__float2bfloat16_rn(v.z), __float2bfloat16_rn(v.w));
        }
    }
    {
        const int f4 = tid & 7, rg = tid >> 3;
        #pragma unroll 8
        for (int it = 0; it < 16; ++it) {
            const int row = rg + it * 16;
            const float4 v = *(const float4*)(pi + (size_t)lbl[row] * 32 + f4 * 4);
            Ps[row * 33 + f4 * 4 + 0] = v.x;
            Ps[row * 33 + f4 * 4 + 1] = v.y;
            Ps[row * 33 + f4 * 4 + 2] = v.z;
            Ps[row * 33 + f4 * 4 + 3] = v.w;
        }
    }
    __syncthreads();   // Xs/Ps visible block-wide

    const int w    = tid >> 5;        // warp 0..3 -> rows w*64 .. w*64+63
    const int lane = tid & 31;
    const int g    = lane >> 2;
    const int t4   = lane & 3;
    const int base = w * 64;

    // A fragments: loaded ONCE, live across the whole k loop (64 regs)
    unsigned aF[4][4][4];
    #pragma unroll
    for (int es = 0; es < 4; ++es) {
        const int e0 = es * 16 + 2 * t4;
        #pragma unroll
        for (int rg = 0; rg < 4; ++rg) {
            const int r = base + rg * 16 + g;
            aF[es][rg][0] = *(const unsigned*)&Xs[r       * SW + e0];
            aF[es][rg][1] = *(const unsigned*)&Xs[(r + 8) * SW + e0];
            aF[es][rg][2] = *(const unsigned*)&Xs[r       * SW + e0 + 8];
            aF[es][rg][3] = *(const unsigned*)&Xs[(r + 8) * SW + e0 + 8];
        }
    }

    // ---- wait for all components (cheap volatile poll, no atomics)
    if (tid == 0) {
        while (*(volatile int*)&g_ready < 32) { __nanosleep(100); }
    }
    __syncthreads();
    __threadfence();
    if (tid < 32) nhc[tid] = g_nhc[tid];

    auto prefetch = [&](int k, int b) {
        const uint4* src = (const uint4*)(g_Wb + k * 4096);
        #pragma unroll
        for (int it = 0; it < 4; ++it) {
            const int idx = tid + it * 128;
            cp_async16(&Ws[b * 64 * SW + (idx >> 3) * SW + (idx & 7) * 8], &src[idx]);
        }
    };

    prefetch(0, 0);
    asm volatile("cp.async.commit_group;\n");

    // 8 independent square-term accumulators
    float accs[4][2];
    #pragma unroll
    for (int rg = 0; rg < 4; ++rg) { accs[rg][0] = 0.f; accs[rg][1] = 0.f; }
    float accc[4] = {0.f, 0.f, 0.f, 0.f};

    #pragma unroll 1
    for (int k = 0; k < 32; ++k) {
        const int buf = k & 1;
        __syncthreads();
        prefetch(k + 1, buf ^ 1);              // k+1 <= 32 always (slot 32 = U)
        asm volatile("cp.async.commit_group;\n");
        asm volatile("cp.async.wait_group 1;\n");
        __syncthreads();

        const __nv_bfloat16* Wk = Ws + buf * 64 * SW;

        float p0[4], p1[4];
        #pragma unroll
        for (int rg = 0; rg < 4; ++rg) {
            const int r = base + rg * 16 + g;
            p0[rg] = Ps[r       * 33 + k];
            p1[rg] = Ps[(r + 8) * 33 + k];
        }

        #pragma unroll
        for (int j = 0; j < 8; ++j) {
            float c0[4], c1[4], c2[4], c3[4];
            #pragma unroll
            for (int rg = 0; rg < 4; ++rg) { c0[rg]=0.f; c1[rg]=0.f; c2[rg]=0.f; c3[rg]=0.f; }
            // lower-triangular W: rows d in [8j, 8j+8) need only e <= 8j+7
            const int esn = j / 2 + 1;
            #pragma unroll
            for (int es = 0; es < esn; ++es) {
                const int e0 = es * 16 + 2 * t4;
                const unsigned b0v = *(const unsigned*)&Wk[(j * 8 + g) * SW + e0];
                const unsigned b1v = *(const unsigned*)&Wk[(j * 8 + g) * SW + e0 + 8];
                #pragma unroll
                for (int rg = 0; rg < 4; ++rg)
                    MMA(c0[rg], c1[rg], c2[rg], c3[rg],
                        aF[es][rg][0], aF[es][rg][1], aF[es][rg][2], aF[es][rg][3],
                        b0v, b1v);
            }
            #pragma unroll
            for (int rg = 0; rg < 4; ++rg) {
                accs[rg][0] = fmaf(p0[rg], fmaf(c0[rg], c0[rg], c1[rg] * c1[rg]), accs[rg][0]);
                accs[rg][1] = fmaf(p1[rg], fmaf(c2[rg], c2[rg], c3[rg] * c3[rg]), accs[rg][1]);
            }
        }
    }

    // ---- pseudo-iteration: cross terms  cross[b][k'] = x_b . u_k'  (U dense)
    asm volatile("cp.async.wait_group 0;\n");
    __syncthreads();
    {
        const __nv_bfloat16* Wu = Ws;          // buffer 0 holds slot 32
        #pragma unroll
        for (int j = 0; j < 4; ++j) {          // k' = j*8 .. j*8+7
            float c0[4], c1[4], c2[4], c3[4];
            #pragma unroll
            for (int rg = 0; rg < 4; ++rg) { c0[rg]=0.f; c1[rg]=0.f; c2[rg]=0.f; c3[rg]=0.f; }
            #pragma unroll
            for (int es = 0; es < 4; ++es) {
                const int e0 = es * 16 + 2 * t4;
                const unsigned b0v = *(const unsigned*)&Wu[(j * 8 + g) * SW + e0];
                const unsigned b1v = *(const unsigned*)&Wu[(j * 8 + g) * SW + e0 + 8];
                #pragma unroll
                for (int rg = 0; rg < 4; ++rg)
                    MMA(c0[rg], c1[rg], c2[rg], c3[rg],
                        aF[es][rg][0], aF[es][rg][1], aF[es][rg][2], aF[es][rg][3],
                        b0v, b1v);
            }
            const int k0 = j * 8 + 2 * t4;
            #pragma unroll
            for (int rg = 0; rg < 4; ++rg) {
                const int r = base + rg * 16 + g;
                float cc;
                cc = fmaf(Ps[r       * 33 + k0],     c0[rg],
                     fmaf(Ps[r       * 33 + k0 + 1], c1[rg], 0.f));
                cc = fmaf(Ps[(r + 8) * 33 + k0],     c2[rg], cc);
                cc = fmaf(Ps[(r + 8) * 33 + k0 + 1], c3[rg], cc);
                accc[rg] += cc;
            }
        }
    }

    // deterministic combine of private partials
    float acc_sq = ((accs[0][0] + accs[0][1]) + (accs[1][0] + accs[1][1]))
                 + ((accs[2][0] + accs[2][1]) + (accs[3][0] + accs[3][1]));
    float acc_cr = (accc[0] + accc[1]) + (accc[2] + accc[3]);
    float acc = fmaf(-0.5f, acc_sq, acc_cr);

    // constant part: rows tid and tid+128
    {
        float c = 0.f;
        #pragma unroll
        for (int kk = 0; kk < 32; ++kk) {
            c = fmaf(Ps[tid * 33 + kk],         nhc[kk], c);
            c = fmaf(Ps[(tid + 128) * 33 + kk], nhc[kk], c);
        }
        acc += c;
    }

    // deterministic block reduction
    red[tid] = acc;
    __syncthreads();
    #pragma unroll
    for (int st = 64; st > 0; st >>= 1) {
        if (tid < st) red[tid] += red[tid + st];
        __syncthreads();
    }
    if (tid == 0) g_part[gbid] = red[0];

    // ---- last block overall: final reduce + reset
    if (tid == 0) {
        __threadfence();
        const int old = atomicAdd(&g_done, 1);
        flg[0] = (old == total - 1) ? 1 : 0;
    }
    __syncthreads();
    if (flg[0]) {
        __threadfence();
        float a = 0.f;
        for (int i = tid; i < nb; i += 128) a += g_part[i];
        red[tid] = a;
        __syncthreads();
        #pragma unroll
        for (int st = 64; st > 0; st >>= 1) {
            if (tid < st) red[tid] += red[tid + st];
            __syncthreads();
        }
        if (tid == 0) {
            out[0] = fabsf(red[0]);
            g_done  = 0;
            g_ready = 0;
        }
    }
}

// ---------------- launch ----------------
extern "C" void kernel_launch(void* const* d_in, const int* in_sizes, int n_in,
                              void* d_out, int out_size)
{
    const float* emb    = (const float*)d_in[0];   // (500000, 64)
    const float* cen    = (const float*)d_in[1];   // (32, 64)
    const float* cov    = (const float*)d_in[2];   // (32, 64, 64)
    const float* pi     = (const float*)d_in[3];   // (500000, 32)
    const int*   labels = (const int*)d_in[4];     // (B,)
    const int B  = in_sizes[4];
    const int nb = B / 256;

    static int configured = 0;
    if (!configured) {
        cudaFuncSetAttribute(fused_kernel, cudaFuncAttributeMaxDynamicSharedMemorySize,
                             SMEM_TOTAL);
        configured = 1;
    }

    fused_kernel<<<nb + 32, 128, SMEM_TOTAL>>>(emb, cen, cov, pi, labels,
                                               (float*)d_out);
}

// round 12
// speedup vs baseline: 1.4293x; 1.0322x over previous
#include <cuda_runtime.h>
#include <cuda_bf16.h>
#include <math.h>

// ---------------- device scratch (no allocations allowed) ----------------
__device__ __nv_bfloat16 g_Wb[33 * 64 * 64]; // [k][d][e]; slot 32 = U (cross)
__device__ float g_nhc[32];                  // -0.5*(D*log2pi + logdet + tau)
__device__ float g_part[4096];               // per-block partial sums
__device__ int   g_ready;                    // # components prepped
__device__ int   g_done;                     // # blocks finished

#define LOG2PI 1.8378770664093453f
#define SW 72    // bf16 smem row stride: conflict-free fragment LDS
#define PSW 36   // Ps float stride: 144B rows (16B-aligned for cp.async)

// dynamic smem layout (bytes). Prep overlays [0, ~34KB) inside Xs region.
#define OFF_XS   0                          // bf16 [256*SW]            36864
#define OFF_WS   36864                      // bf16 [3][64*SW]          27648
#define OFF_PS   64512                      // float [256*PSW]          36864
#define OFF_NHC  101376                     // float [32]                 128
#define OFF_LBL  101504                     // int   [256]               1024
#define OFF_RED  102528                     // float [128]                512
#define OFF_FLG  103040                     // int                         16
#define SMEM_TOTAL 103056

__device__ __forceinline__ void cp_async16(void* dst, const void* src) {
    unsigned a = (unsigned)__cvta_generic_to_shared(dst);
    asm volatile("cp.async.ca.shared.global [%0], [%1], 16;\n" :: "r"(a), "l"(src));
}

#define MMA(c0,c1,c2,c3,a0,a1,a2,a3,b0,b1)                                   \
    asm volatile(                                                            \
        "mma.sync.aligned.m16n8k16.row.col.f32.bf16.bf16.f32 "               \
        "{%0,%1,%2,%3}, {%4,%5,%6,%7}, {%8,%9}, {%0,%1,%2,%3};\n"            \
        : "+f"(c0), "+f"(c1), "+f"(c2), "+f"(c3)                             \
        : "r"(a0), "r"(a1), "r"(a2), "r"(a3), "r"(b0), "r"(b1))

// ---------------- prep (device fn, 128 threads) -------------------------------
__device__ void do_prep(int k, const float* __restrict__ cov,
                        const float* __restrict__ cen, char* smem_raw, int tid)
{
    float* A    = (float*)smem_raw;          // 64*65
    float* Li   = A  + 64 * 65;              // 64*65
    float* rd   = Li + 64 * 65;              // 64
    float* dl   = rd + 64;                   // 64
    float* tsm  = dl + 64;                   // 64

    const int l = tid & 31;

    for (int idx = tid; idx < 4096; idx += 128)
        A[(idx >> 6) * 65 + (idx & 63)] = cov[k * 4096 + idx];
    __syncthreads();

    // blocked right-looking Cholesky: 8 panels of 8 columns
    #pragma unroll 1
    for (int p = 0; p < 8; ++p) {
        const int c0 = p * 8;
        if (tid < 32) {                       // panel: warp 0, register-resident
            const int r0 = c0 + l, r1 = c0 + 32 + l;
            const bool act0 = (r0 < 64), act1 = (r1 < 64);
            float a0[8], a1[8];
            #pragma unroll
            for (int m = 0; m < 8; ++m) {
                a0[m] = act0 ? A[r0 * 65 + c0 + m] : 0.f;
                a1[m] = act1 ? A[r1 * 65 + c0 + m] : 0.f;
            }
            #pragma unroll
            for (int jj = 0; jj < 8; ++jj) {
                const float d = __shfl_sync(0xffffffffu, a0[jj], jj);
                const float rs = rsqrtf(d);
                if (act0 && l >= jj) a0[jj] *= rs;
                if (act1)            a1[jj] *= rs;
                float lv[8];
                #pragma unroll
                for (int m = jj + 1; m < 8; ++m)
                    lv[m] = __shfl_sync(0xffffffffu, a0[jj], m);
                #pragma unroll
                for (int m = jj + 1; m < 8; ++m) {
                    if (act0 && l > jj) a0[m] -= a0[jj] * lv[m];
                    if (act1)           a1[m] -= a1[jj] * lv[m];
                }
            }
            #pragma unroll
            for (int m = 0; m < 8; ++m) {
                if (act0) A[r0 * 65 + c0 + m] = a0[m];
                if (act1) A[r1 * 65 + c0 + m] = a1[m];
            }
        }
        __syncthreads();
        // trailing rank-8 update, lower triangle only; 128 threads
        const int R = 56 - c0;
        if (R > 0) {
            const int rr = tid >> 1, cq = tid & 1;
            if (rr < R) {
                const int r = c0 + 8 + rr;
                float pr[8];
                #pragma unroll
                for (int m = 0; m < 8; ++m) pr[m] = A[r * 65 + c0 + m];
                #pragma unroll 4
                for (int cc = cq; cc <= rr; cc += 2) {
                    const int c = c0 + 8 + cc;
                    float s0 = A[r * 65 + c], s1 = 0.f;
                    #pragma unroll
                    for (int m = 0; m < 4; ++m) {
                        s0 -= pr[m]     * A[c * 65 + c0 + m];
                        s1 += pr[m + 4] * A[c * 65 + c0 + m + 4];
                    }
                    A[r * 65 + c] = s0 - s1;
                }
            }
        }
        __syncthreads();
    }

    if (tid < 64) {
        const float dii = A[tid * 65 + tid];
        dl[tid] = 2.f * logf(dii);
        rd[tid] = 1.0f / dii;
    }
    __syncthreads();

    // forward substitution: 4 warps x 16 columns each
    {
        const int w = tid >> 5;
        const int r0 = l, r1 = l + 32;
        const int c0 = w * 16;
        float v0[16], v1[16];
        #pragma unroll
        for (int j = 0; j < 16; ++j) {
            v0[j] = (r0 == c0 + j) ? 1.f : 0.f;
            v1[j] = (r1 == c0 + j) ? 1.f : 0.f;
        }
        for (int m = 0; m < 64; ++m) {
            const float lr0 = (r0 > m) ? A[r0 * 65 + m] : 0.f;
            const float lr1 = (r1 > m) ? A[r1 * 65 + m] : 0.f;
            const float rdm = rd[m];
            const int   src = m & 31;
            const bool  lo  = (m < 32);
            #pragma unroll
            for (int j = 0; j < 16; ++j) {
                const float resid = lo ? v0[j] : v1[j];
                const float ym = __shfl_sync(0xffffffffu, resid, src) * rdm;
                v0[j] -= lr0 * ym;
                v1[j] -= lr1 * ym;
                if (l == src) Li[m * 65 + c0 + j] = ym;
            }
        }
    }
    __syncthreads();

    // t = Linv * c (fp32), 4-way partials
    if (tid < 64) {
        float s0 = 0.f, s1 = 0.f, s2 = 0.f, s3 = 0.f;
        int e = 0;
        for (; e + 3 <= tid; e += 4) {
            s0 += Li[tid * 65 + e]     * cen[k * 64 + e];
            s1 += Li[tid * 65 + e + 1] * cen[k * 64 + e + 1];
            s2 += Li[tid * 65 + e + 2] * cen[k * 64 + e + 2];
            s3 += Li[tid * 65 + e + 3] * cen[k * 64 + e + 3];
        }
        for (; e <= tid; ++e) s0 += Li[tid * 65 + e] * cen[k * 64 + e];
        tsm[tid] = (s0 + s1) + (s2 + s3);
    }
    __syncthreads();

    // u = Linv^T t (row k of the cross matrix, bf16), 4-way partials
    if (tid < 64) {
        const int e = tid;
        float s0 = 0.f, s1 = 0.f, s2 = 0.f, s3 = 0.f;
        int d = e;
        for (; d + 3 < 64; d += 4) {
            s0 += Li[d * 65 + e]       * tsm[d];
            s1 += Li[(d + 1) * 65 + e] * tsm[d + 1];
            s2 += Li[(d + 2) * 65 + e] * tsm[d + 2];
            s3 += Li[(d + 3) * 65 + e] * tsm[d + 3];
        }
        for (; d < 64; ++d) s0 += Li[d * 65 + e] * tsm[d];
        g_Wb[32 * 4096 + k * 64 + e] = __float2bfloat16_rn((s0 + s1) + (s2 + s3));
    }
    if (tid == 0) {
        float ld = 0.f, tau = 0.f;
        #pragma unroll 4
        for (int m = 0; m < 64; ++m) { ld += dl[m]; tau += tsm[m] * tsm[m]; }
        g_nhc[k] = -0.5f * (64.f * LOG2PI + ld + tau);
    }
    // bf16 W
    #pragma unroll 4
    for (int idx = tid; idx < 4096; idx += 128) {
        const int d = idx >> 6, e = idx & 63;
        const float v = (e <= d) ? Li[d * 65 + e] : 0.f;
        g_Wb[k * 4096 + idx] = __float2bfloat16_rn(v);
    }
}

// ---------------- single fused kernel -----------------------------------------
// grid = 32 prep blocks + B/256 GEMM blocks; block = 128 threads
__global__ void __launch_bounds__(128, 2) fused_kernel(const float* __restrict__ emb,
                                                       const float* __restrict__ cen,
                                                       const float* __restrict__ cov,
                                                       const float* __restrict__ pi,
                                                       const int* __restrict__ labels,
                                                       float* __restrict__ out)
{
    extern __shared__ char smem[];
    __nv_bfloat16* Xs  = (__nv_bfloat16*)(smem + OFF_XS);
    __nv_bfloat16* Ws  = (__nv_bfloat16*)(smem + OFF_WS);   // [3][64*SW]
    float* Ps  = (float*)(smem + OFF_PS);
    float* nhc = (float*)(smem + OFF_NHC);
    int*   lbl = (int*)  (smem + OFF_LBL);
    float* red = (float*)(smem + OFF_RED);
    int*   flg = (int*)  (smem + OFF_FLG);

    const int tid   = threadIdx.x;
    const int total = gridDim.x;         // nb + 32
    const int nb    = total - 32;

    // =================== prep blocks: prep only, then exit =====================
    if (blockIdx.x < 32) {
        do_prep(blockIdx.x, cov, cen, smem, tid);
        __syncthreads();
        if (tid == 0) {
            __threadfence();
            atomicAdd(&g_ready, 1);
            __threadfence();
            const int old = atomicAdd(&g_done, 1);
            flg[0] = (old == total - 1) ? 1 : 0;
        }
        __syncthreads();
        if (flg[0]) {                    // defensive: never last in practice
            __threadfence();
            float a = 0.f;
            for (int i = tid; i < nb; i += 128) a += g_part[i];
            red[tid] = a;
            __syncthreads();
            #pragma unroll
            for (int st = 64; st > 0; st >>= 1) {
                if (tid < st) red[tid] += red[tid + st];
                __syncthreads();
            }
            if (tid == 0) { out[0] = fabsf(red[0]); g_done = 0; g_ready = 0; }
        }
        return;
    }

    // =================== GEMM blocks ==========================================
    const int gbid = blockIdx.x - 32;
    const int b0   = gbid * 256;

    lbl[tid]       = labels[b0 + tid];
    lbl[tid + 128] = labels[b0 + tid + 128];
    __syncthreads();

    // ---- pi gather via cp.async (group A; completion checked at k=0 wait)
    {
        #pragma unroll
        for (int it = 0; it < 16; ++it) {
            const int idx = tid + it * 128;
            const int row = idx >> 3, c8 = idx & 7;
            cp_async16(&Ps[row * PSW + c8 * 4],
                       pi + (size_t)lbl[row] * 32 + c8 * 4);
        }
    }
    asm volatile("cp.async.commit_group;\n");

    // ---- emb gather -> bf16 Xs (overlaps prep blocks' work)
    {
        const int f4 = tid & 15, rg = tid >> 4;
        #pragma unroll 8
        for (int it = 0; it < 32; ++it) {
            const int row = rg + it * 8;
            const float4 v = *(const float4*)(emb + (size_t)lbl[row] * 64 + f4 * 4);
            __nv_bfloat162* p = (__nv_bfloat162*)&Xs[row * SW + f4 * 4];
            p[0] = __nv_bfloat162(__float2bfloat16_rn(v.x), __float2bfloat16_rn(v.y));
            p[1] = __nv_bfloat162(__float2bfloat16_rn(v.z), __float2bfloat16_rn(v.w));
        }
    }
    __syncthreads();   // Xs visible block-wide

    const int w    = tid >> 5;        // warp 0..3 -> rows w*64 .. w*64+63
    const int lane = tid & 31;
    const int g    = lane >> 2;
    const int t4   = lane & 3;
    const int base = w * 64;

    // A fragments: loaded ONCE, live across the whole k loop (64 regs)
    unsigned aF[4][4][4];
    #pragma unroll
    for (int es = 0; es < 4; ++es) {
        const int e0 = es * 16 + 2 * t4;
        #pragma unroll
        for (int rg = 0; rg < 4; ++rg) {
            const int r = base + rg * 16 + g;
            aF[es][rg][0] = *(const unsigned*)&Xs[r       * SW + e0];
            aF[es][rg][1] = *(const unsigned*)&Xs[(r + 8) * SW + e0];
            aF[es][rg][2] = *(const unsigned*)&Xs[r       * SW + e0 + 8];
            aF[es][rg][3] = *(const unsigned*)&Xs[(r + 8) * SW + e0 + 8];
        }
    }

    // ---- wait for all components (cheap volatile poll)
    if (tid == 0) {
        while (*(volatile int*)&g_ready < 32) { __nanosleep(100); }
    }
    __syncthreads();
    __threadfence();
    if (tid < 32) nhc[tid] = g_nhc[tid];

    auto prefetch = [&](int k, int slot) {
        const uint4* src = (const uint4*)(g_Wb + k * 4096);
        #pragma unroll
        for (int it = 0; it < 4; ++it) {
            const int idx = tid + it * 128;
            cp_async16(&Ws[slot * 64 * SW + (idx >> 3) * SW + (idx & 7) * 8],
                       &src[idx]);
        }
    };

    prefetch(0, 0);
    asm volatile("cp.async.commit_group;\n");
    prefetch(1, 1);
    asm volatile("cp.async.commit_group;\n");

    // 8 independent square-term accumulators + 4 cross accumulators
    float accs[4][2];
    #pragma unroll
    for (int rg = 0; rg < 4; ++rg) { accs[rg][0] = 0.f; accs[rg][1] = 0.f; }
    float accc[4] = {0.f, 0.f, 0.f, 0.f};

    // ---- main loop: ONE barrier per iteration, 3-slot ring; k=32 is U/cross
    #pragma unroll 1
    for (int k = 0; k <= 32; ++k) {
        asm volatile("cp.async.wait_group 1;\n");   // group k landed
        __syncthreads();                            // visible + slot (k+2)%3 free
        if (k + 2 <= 32) prefetch(k + 2, (k + 2) % 3);
        asm volatile("cp.async.commit_group;\n");   // (empty group ok)

        const __nv_bfloat16* Wk = Ws + (k % 3) * 64 * SW;

        if (k < 32) {
            // raw quad partials this k (p applied once after the j-loop)
            float q0[4] = {0.f, 0.f, 0.f, 0.f};
            float q1[4] = {0.f, 0.f, 0.f, 0.f};

            #pragma unroll
            for (int j = 0; j < 8; ++j) {
                float c0[4], c1[4], c2[4], c3[4];
                #pragma unroll
                for (int rg = 0; rg < 4; ++rg) { c0[rg]=0.f; c1[rg]=0.f; c2[rg]=0.f; c3[rg]=0.f; }
                // lower-triangular W: rows d in [8j, 8j+8) need only e <= 8j+7
                const int esn = j / 2 + 1;
                #pragma unroll
                for (int es = 0; es < esn; ++es) {
                    const int e0 = es * 16 + 2 * t4;
                    const unsigned b0v = *(const unsigned*)&Wk[(j * 8 + g) * SW + e0];
                    const unsigned b1v = *(const unsigned*)&Wk[(j * 8 + g) * SW + e0 + 8];
                    #pragma unroll
                    for (int rg = 0; rg < 4; ++rg)
                        MMA(c0[rg], c1[rg], c2[rg], c3[rg],
                            aF[es][rg][0], aF[es][rg][1], aF[es][rg][2], aF[es][rg][3],
                            b0v, b1v);
                }
                #pragma unroll
                for (int rg = 0; rg < 4; ++rg) {
                    q0[rg] = fmaf(c0[rg], c0[rg], q0[rg]);
                    q0[rg] = fmaf(c1[rg], c1[rg], q0[rg]);
                    q1[rg] = fmaf(c2[rg], c2[rg], q1[rg]);
                    q1[rg] = fmaf(c3[rg], c3[rg], q1[rg]);
                }
            }
            #pragma unroll
            for (int rg = 0; rg < 4; ++rg) {
                const int r = base + rg * 16 + g;
                accs[rg][0] = fmaf(Ps[r       * PSW + k], q0[rg], accs[rg][0]);
                accs[rg][1] = fmaf(Ps[(r + 8) * PSW + k], q1[rg], accs[rg][1]);
            }
        } else {
            // cross terms: cross[b][k'] = x_b . u_k'  (U dense)
            #pragma unroll
            for (int j = 0; j < 4; ++j) {          // k' = j*8 .. j*8+7
                float c0[4], c1[4], c2[4], c3[4];
                #pragma unroll
                for (int rg = 0; rg < 4; ++rg) { c0[rg]=0.f; c1[rg]=0.f; c2[rg]=0.f; c3[rg]=0.f; }
                #pragma unroll
                for (int es = 0; es < 4; ++es) {
                    const int e0 = es * 16 + 2 * t4;
                    const unsigned b0v = *(const unsigned*)&Wk[(j * 8 + g) * SW + e0];
                    const unsigned b1v = *(const unsigned*)&Wk[(j * 8 + g) * SW + e0 + 8];
                    #pragma unroll
                    for (int rg = 0; rg < 4; ++rg)
                        MMA(c0[rg], c1[rg], c2[rg], c3[rg],
                            aF[es][rg][0], aF[es][rg][1], aF[es][rg][2], aF[es][rg][3],
                            b0v, b1v);
                }
                const int k0 = j * 8 + 2 * t4;
                #pragma unroll
                for (int rg = 0; rg < 4; ++rg) {
                    const int r = base + rg * 16 + g;
                    float cc;
                    cc = fmaf(Ps[r       * PSW + k0],     c0[rg],
                         fmaf(Ps[r       * PSW + k0 + 1], c1[rg], 0.f));
                    cc = fmaf(Ps[(r + 8) * PSW + k0],     c2[rg], cc);
                    cc = fmaf(Ps[(r + 8) * PSW + k0 + 1], c3[rg], cc);
                    accc[rg] += cc;
                }
            }
        }
    }

    // deterministic combine of private partials
    float acc_sq = ((accs[0][0] + accs[0][1]) + (accs[1][0] + accs[1][1]))
                 + ((accs[2][0] + accs[2][1]) + (accs[3][0] + accs[3][1]));
    float acc_cr = (accc[0] + accc[1]) + (accc[2] + accc[3]);
    float acc = fmaf(-0.5f, acc_sq, acc_cr);

    // constant part: rows tid and tid+128
    {
        float c = 0.f;
        #pragma unroll
        for (int kk = 0; kk < 32; ++kk) {
            c = fmaf(Ps[tid * PSW + kk],         nhc[kk], c);
            c = fmaf(Ps[(tid + 128) * PSW + kk], nhc[kk], c);
        }
        acc += c;
    }

    // deterministic block reduction
    red[tid] = acc;
    __syncthreads();
    #pragma unroll
    for (int st = 64; st > 0; st >>= 1) {
        if (tid < st) red[tid] += red[tid + st];
        __syncthreads();
    }
    if (tid == 0) g_part[gbid] = red[0];

    // ---- last block overall: final reduce + reset
    if (tid == 0) {
        __threadfence();
        const int old = atomicAdd(&g_done, 1);
        flg[0] = (old == total - 1) ? 1 : 0;
    }
    __syncthreads();
    if (flg[0]) {
        __threadfence();
        float a = 0.f;
        for (int i = tid; i < nb; i += 128) a += g_part[i];
        red[tid] = a;
        __syncthreads();
        #pragma unroll
        for (int st = 64; st > 0; st >>= 1) {
            if (tid < st) red[tid] += red[tid + st];
            __syncthreads();
        }
        if (tid == 0) {
            out[0] = fabsf(red[0]);
            g_done  = 0;
            g_ready = 0;
        }
    }
}

// ---------------- launch ----------------
extern "C" void kernel_launch(void* const* d_in, const int* in_sizes, int n_in,
                              void* d_out, int out_size)
{
    const float* emb    = (const float*)d_in[0];   // (500000, 64)
    const float* cen    = (const float*)d_in[1];   // (32, 64)
    const float* cov    = (const float*)d_in[2];   // (32, 64, 64)
    const float* pi     = (const float*)d_in[3];   // (500000, 32)
    const int*   labels = (const int*)d_in[4];     // (B,)
    const int B  = in_sizes[4];
    const int nb = B / 256;

    static int configured = 0;
    if (!configured) {
        cudaFuncSetAttribute(fused_kernel, cudaFuncAttributeMaxDynamicSharedMemorySize,
                             SMEM_TOTAL);
        configured = 1;
    }

    fused_kernel<<<nb + 32, 128, SMEM_TOTAL>>>(emb, cen, cov, pi, labels,
                                               (float*)d_out);
}